// round 1
// baseline (speedup 1.0000x reference)
#include <cuda_runtime.h>
#include <math.h>

#define B_   2
#define L_   2048
#define H_   2048
#define NH_  16
#define KVH_ 4
#define G_   4
#define D_   128
#define SCALE 0.08838834764831845f   // 1/sqrt(128)

// ---------------- scratch (static device globals; no allocation) ----------------
__device__ float g_qT[(size_t)B_ * NH_ * D_ * L_];   // [b,h,d,l]  33.5MB
__device__ float g_kT[(size_t)B_ * KVH_ * D_ * L_];  // [b,kvh,d,l] 8.4MB
__device__ float g_v [(size_t)B_ * KVH_ * L_ * D_];  // [b,kvh,l,d] 8.4MB
__device__ float g_at[(size_t)B_ * L_ * H_];         // attention out [b,l,h*d]
__device__ float g_pr[(size_t)B_ * L_ * H_];         // o-proj out

#define MODE_PLAIN 0
#define MODE_QK    1
#define MODE_V     2

// ---------------- GEMM: C = A[M,K] @ W[N,K]^T + bias, with scatter modes ----------------
__global__ __launch_bounds__(256, 2)
void gemm_tn(const float* __restrict__ A,
             const float* __restrict__ W, const float* __restrict__ bias, float* __restrict__ C, int mode,
             int N, int K, int heads,
             const float* __restrict__ W2, const float* __restrict__ bias2, float* __restrict__ C2, int mode2)
{
    if (blockIdx.z == 1) { W = W2; bias = bias2; C = C2; mode = mode2; }

    __shared__ __align__(16) float As[16][128];
    __shared__ __align__(16) float Bs[16][128];

    int tid = threadIdx.x;
    int tx = tid & 15, ty = tid >> 4;
    int m0 = blockIdx.y * 128;
    int n0 = blockIdx.x * 128;

    const float* Ab = A + (size_t)m0 * K;
    const float* Wb = W + (size_t)n0 * K;

    float c[8][8];
#pragma unroll
    for (int i = 0; i < 8; i++)
#pragma unroll
        for (int j = 0; j < 8; j++) c[i][j] = 0.f;

    for (int k0 = 0; k0 < K; k0 += 16) {
#pragma unroll
        for (int it = 0; it < 2; it++) {
            int id = tid + it * 256;
            int row = id >> 2;
            int kk = (id & 3) << 2;
            float4 av = *(const float4*)(Ab + (size_t)row * K + k0 + kk);
            As[kk + 0][row] = av.x; As[kk + 1][row] = av.y;
            As[kk + 2][row] = av.z; As[kk + 3][row] = av.w;
            float4 bv = *(const float4*)(Wb + (size_t)row * K + k0 + kk);
            Bs[kk + 0][row] = bv.x; Bs[kk + 1][row] = bv.y;
            Bs[kk + 2][row] = bv.z; Bs[kk + 3][row] = bv.w;
        }
        __syncthreads();
#pragma unroll
        for (int k = 0; k < 16; k++) {
            float4 a0 = *(float4*)&As[k][ty * 8];
            float4 a1 = *(float4*)&As[k][ty * 8 + 4];
            float4 b0 = *(float4*)&Bs[k][tx * 8];
            float4 b1 = *(float4*)&Bs[k][tx * 8 + 4];
            float av[8] = {a0.x, a0.y, a0.z, a0.w, a1.x, a1.y, a1.z, a1.w};
            float bv[8] = {b0.x, b0.y, b0.z, b0.w, b1.x, b1.y, b1.z, b1.w};
#pragma unroll
            for (int i = 0; i < 8; i++)
#pragma unroll
                for (int j = 0; j < 8; j++) c[i][j] = fmaf(av[i], bv[j], c[i][j]);
        }
        __syncthreads();
    }

    int b  = m0 / L_;
    int l0 = m0 % L_;

    if (mode == MODE_PLAIN) {
#pragma unroll
        for (int i = 0; i < 8; i++) {
            int m = m0 + ty * 8 + i;
            float* cp = C + (size_t)m * N + n0 + tx * 8;
#pragma unroll
            for (int j = 0; j < 8; j++) cp[j] = c[i][j] + bias[n0 + tx * 8 + j];
        }
    } else if (mode == MODE_QK) {
        // out[((b*heads + h)*D + d)*L + l], h = n0/128 (tile aligned to head), d = tx*8+j
        int h = n0 / D_;
        float* base = C + ((size_t)(b * heads + h)) * D_ * L_;
#pragma unroll
        for (int j = 0; j < 8; j++) {
            int d = tx * 8 + j;
            float bsv = bias[n0 + tx * 8 + j];
            float4 v0 = make_float4(c[0][j] + bsv, c[1][j] + bsv, c[2][j] + bsv, c[3][j] + bsv);
            float4 v1 = make_float4(c[4][j] + bsv, c[5][j] + bsv, c[6][j] + bsv, c[7][j] + bsv);
            *(float4*)(base + (size_t)d * L_ + l0 + ty * 8)     = v0;
            *(float4*)(base + (size_t)d * L_ + l0 + ty * 8 + 4) = v1;
        }
    } else { // MODE_V: out[((b*heads + h)*L + l)*D + d]
        int h = n0 / D_;
        float* base = C + ((size_t)(b * heads + h)) * L_ * D_;
#pragma unroll
        for (int i = 0; i < 8; i++) {
            int l = l0 + ty * 8 + i;
            float* cp = base + (size_t)l * D_ + tx * 8;
#pragma unroll
            for (int j = 0; j < 8; j++) cp[j] = c[i][j] + bias[n0 + tx * 8 + j];
        }
    }
}

// ---------------- Flash attention: per (b,h), 64 q-rows x 128 kv-cols tiles ----------------
__global__ __launch_bounds__(256, 1)
void attn_kernel(const float* __restrict__ qT, const float* __restrict__ kT,
                 const float* __restrict__ vbuf, const float* __restrict__ mask,
                 float* __restrict__ attn)
{
    extern __shared__ float sm[];
    float* Qt = sm;                    // [128 d][64 r]
    float* Kt = Qt + 128 * 64;         // [128 d][128 c]
    float* Vs = Kt + 128 * 128;        // [128 c][128 d]
    float* Pt = Vs + 128 * 128;        // [128 c][64 r]

    int tid = threadIdx.x;
    int tx = tid & 15;
    int ty = tid >> 4;
    int bh = blockIdx.y;
    int b = bh / NH_;
    int h = bh % NH_;
    int kvh = h / G_;
    int q0 = blockIdx.x * 64;

    const float* qTh = qT + ((size_t)(b * NH_ + h)) * D_ * L_;
    const float* kTh = kT + ((size_t)(b * KVH_ + kvh)) * D_ * L_;
    const float* vh  = vbuf + ((size_t)(b * KVH_ + kvh)) * L_ * D_;
    const float* mrow = mask + (size_t)b * L_;

    // load Q tile [d][r] (producer already stored transposed)
#pragma unroll
    for (int it = 0; it < 8; it++) {
        int id = tid + it * 256;
        int d = id >> 4;
        int r4 = (id & 15) << 2;
        *(float4*)&Qt[d * 64 + r4] = *(const float4*)&qTh[(size_t)d * L_ + q0 + r4];
    }

    float o[4][8];
#pragma unroll
    for (int i = 0; i < 4; i++)
#pragma unroll
        for (int j = 0; j < 8; j++) o[i][j] = 0.f;
    float m_run[4], l_run[4];
#pragma unroll
    for (int i = 0; i < 4; i++) { m_run[i] = -1e30f; l_run[i] = 0.f; }

    for (int kt = 0; kt < L_ / 128; kt++) {
        int c0 = kt * 128;
        __syncthreads();  // protect Kt/Vs/Pt from previous iteration consumers
#pragma unroll
        for (int it = 0; it < 16; it++) {
            int id = tid + it * 256;
            int r = id >> 5;
            int c4 = (id & 31) << 2;
            *(float4*)&Kt[r * 128 + c4] = *(const float4*)&kTh[(size_t)r * L_ + c0 + c4];
            *(float4*)&Vs[r * 128 + c4] = *(const float4*)&vh[(size_t)(c0 + r) * D_ + c4];
        }
        __syncthreads();

        // S = Q K^T  (rows ty*4+i, cols tx*8+j)
        float s[4][8];
#pragma unroll
        for (int i = 0; i < 4; i++)
#pragma unroll
            for (int j = 0; j < 8; j++) s[i][j] = 0.f;

#pragma unroll 4
        for (int d = 0; d < 128; d++) {
            float4 a  = *(float4*)&Qt[d * 64 + ty * 4];
            float4 b0 = *(float4*)&Kt[d * 128 + tx * 8];
            float4 b1 = *(float4*)&Kt[d * 128 + tx * 8 + 4];
            float av[4] = {a.x, a.y, a.z, a.w};
            float bv[8] = {b0.x, b0.y, b0.z, b0.w, b1.x, b1.y, b1.z, b1.w};
#pragma unroll
            for (int i = 0; i < 4; i++)
#pragma unroll
                for (int j = 0; j < 8; j++) s[i][j] = fmaf(av[i], bv[j], s[i][j]);
        }

        float mv[8];
#pragma unroll
        for (int j = 0; j < 8; j++) mv[j] = mrow[c0 + tx * 8 + j];

#pragma unroll
        for (int i = 0; i < 4; i++) {
            float mx = -1e30f;
#pragma unroll
            for (int j = 0; j < 8; j++) {
                s[i][j] = s[i][j] * SCALE + mv[j];
                mx = fmaxf(mx, s[i][j]);
            }
            mx = fmaxf(mx, __shfl_xor_sync(0xffffffffu, mx, 8));
            mx = fmaxf(mx, __shfl_xor_sync(0xffffffffu, mx, 4));
            mx = fmaxf(mx, __shfl_xor_sync(0xffffffffu, mx, 2));
            mx = fmaxf(mx, __shfl_xor_sync(0xffffffffu, mx, 1));
            float mn = fmaxf(m_run[i], mx);
            float al = __expf(m_run[i] - mn);
            float rs = 0.f;
#pragma unroll
            for (int j = 0; j < 8; j++) {
                float p = __expf(s[i][j] - mn);
                s[i][j] = p;
                rs += p;
            }
            rs += __shfl_xor_sync(0xffffffffu, rs, 8);
            rs += __shfl_xor_sync(0xffffffffu, rs, 4);
            rs += __shfl_xor_sync(0xffffffffu, rs, 2);
            rs += __shfl_xor_sync(0xffffffffu, rs, 1);
            l_run[i] = l_run[i] * al + rs;
            m_run[i] = mn;
#pragma unroll
            for (int j = 0; j < 8; j++) o[i][j] *= al;
        }

        // stage P as [c][r]
#pragma unroll
        for (int j = 0; j < 8; j++) {
            float4 pv = make_float4(s[0][j], s[1][j], s[2][j], s[3][j]);
            *(float4*)&Pt[(tx * 8 + j) * 64 + ty * 4] = pv;
        }
        __syncthreads();

        // O += P V   (rows ty*4+i, dcols tx*8+j)
#pragma unroll 4
        for (int cc = 0; cc < 128; cc++) {
            float4 a  = *(float4*)&Pt[cc * 64 + ty * 4];
            float4 v0 = *(float4*)&Vs[cc * 128 + tx * 8];
            float4 v1 = *(float4*)&Vs[cc * 128 + tx * 8 + 4];
            float av[4] = {a.x, a.y, a.z, a.w};
            float vv[8] = {v0.x, v0.y, v0.z, v0.w, v1.x, v1.y, v1.z, v1.w};
#pragma unroll
            for (int i = 0; i < 4; i++)
#pragma unroll
                for (int j = 0; j < 8; j++) o[i][j] = fmaf(av[i], vv[j], o[i][j]);
        }
    }

#pragma unroll
    for (int i = 0; i < 4; i++) {
        float inv = 1.f / l_run[i];
        int row = q0 + ty * 4 + i;
        float* op = attn + ((size_t)(b * L_ + row)) * H_ + h * D_ + tx * 8;
        float4 v0 = make_float4(o[i][0] * inv, o[i][1] * inv, o[i][2] * inv, o[i][3] * inv);
        float4 v1 = make_float4(o[i][4] * inv, o[i][5] * inv, o[i][6] * inv, o[i][7] * inv);
        *(float4*)op       = v0;
        *(float4*)(op + 4) = v1;
    }
}

// ---------------- residual + LayerNorm, one block per row ----------------
__global__ __launch_bounds__(256)
void ln_kernel(const float* __restrict__ proj, const float* __restrict__ x,
               const float* __restrict__ g, const float* __restrict__ bb,
               float* __restrict__ out)
{
    __shared__ float red[8];
    __shared__ float s_mu, s_rstd;
    int row = blockIdx.x;
    int tid = threadIdx.x;
    const float* pr = proj + (size_t)row * H_;
    const float* xr = x + (size_t)row * H_;

    float vals[8];
    float sum = 0.f;
#pragma unroll
    for (int t = 0; t < 8; t++) {
        int ci = tid + t * 256;
        float v = pr[ci] + xr[ci];
        vals[t] = v;
        sum += v;
    }
    for (int s = 16; s; s >>= 1) sum += __shfl_xor_sync(0xffffffffu, sum, s);
    if ((tid & 31) == 0) red[tid >> 5] = sum;
    __syncthreads();
    if (tid < 32) {
        float v = (tid < 8) ? red[tid] : 0.f;
        for (int s = 4; s; s >>= 1) v += __shfl_xor_sync(0xffffffffu, v, s);
        if (tid == 0) s_mu = v * (1.f / H_);
    }
    __syncthreads();
    float mu = s_mu;
    float vs = 0.f;
#pragma unroll
    for (int t = 0; t < 8; t++) {
        float dv = vals[t] - mu;
        vs += dv * dv;
    }
    for (int s = 16; s; s >>= 1) vs += __shfl_xor_sync(0xffffffffu, vs, s);
    if ((tid & 31) == 0) red[tid >> 5] = vs;
    __syncthreads();
    if (tid < 32) {
        float v = (tid < 8) ? red[tid] : 0.f;
        for (int s = 4; s; s >>= 1) v += __shfl_xor_sync(0xffffffffu, v, s);
        if (tid == 0) s_rstd = rsqrtf(v * (1.f / H_) + 1e-12f);
    }
    __syncthreads();
    float rstd = s_rstd;
#pragma unroll
    for (int t = 0; t < 8; t++) {
        int ci = tid + t * 256;
        out[(size_t)row * H_ + ci] = (vals[t] - mu) * rstd * g[ci] + bb[ci];
    }
}

// ---------------- launch ----------------
extern "C" void kernel_launch(void* const* d_in, const int* in_sizes, int n_in,
                              void* d_out, int out_size)
{
    const float* x    = (const float*)d_in[0];
    const float* mask = (const float*)d_in[1];
    const float* Wq   = (const float*)d_in[2];
    const float* bq   = (const float*)d_in[3];
    const float* Wk   = (const float*)d_in[4];
    const float* bk   = (const float*)d_in[5];
    const float* Wv   = (const float*)d_in[6];
    const float* bv   = (const float*)d_in[7];
    const float* Wo   = (const float*)d_in[8];
    const float* bo   = (const float*)d_in[9];
    const float* lng  = (const float*)d_in[10];
    const float* lnb  = (const float*)d_in[11];
    float* out = (float*)d_out;

    float *qT, *kT, *vb, *at, *pr;
    cudaGetSymbolAddress((void**)&qT, g_qT);
    cudaGetSymbolAddress((void**)&kT, g_kT);
    cudaGetSymbolAddress((void**)&vb, g_v);
    cudaGetSymbolAddress((void**)&at, g_at);
    cudaGetSymbolAddress((void**)&pr, g_pr);

    cudaFuncSetAttribute((const void*)attn_kernel,
                         cudaFuncAttributeMaxDynamicSharedMemorySize, 196608);

    // Q projection -> qT [b,h,d,l]
    gemm_tn<<<dim3(16, 32, 1), 256>>>(x, Wq, bq, qT, MODE_QK, H_, H_, NH_,
                                      Wq, bq, qT, MODE_QK);
    // K (transposed) + V (row-major) in one launch via blockIdx.z
    gemm_tn<<<dim3(4, 32, 2), 256>>>(x, Wk, bk, kT, MODE_QK, KVH_ * D_, H_, KVH_,
                                     Wv, bv, vb, MODE_V);
    // attention
    attn_kernel<<<dim3(L_ / 64, B_ * NH_), 256, 196608>>>(qT, kT, vb, mask, at);
    // O projection
    gemm_tn<<<dim3(16, 32, 1), 256>>>(at, Wo, bo, pr, MODE_PLAIN, H_, H_, 0,
                                      Wo, bo, pr, MODE_PLAIN);
    // residual + layernorm
    ln_kernel<<<B_ * L_, 256>>>(pr, x, lng, lnb, out);
}

// round 4
// speedup vs baseline: 3.1597x; 3.1597x over previous
#include <cuda_runtime.h>
#include <math.h>

#define B_   2
#define L_   2048
#define H_   2048
#define NH_  16
#define KVH_ 4
#define G_   4
#define D_   128
#define SCALE 0.08838834764831845f   // 1/sqrt(128)

// ---------------- scratch ----------------
__device__ float g_q [(size_t)B_ * NH_  * L_ * D_];  // [b,h,l,d]  tf32 bits
__device__ float g_k [(size_t)B_ * KVH_ * L_ * D_];  // [b,kvh,l,d] tf32 bits
__device__ float g_vt[(size_t)B_ * KVH_ * D_ * L_];  // [b,kvh,d,l] tf32 bits
__device__ float g_at[(size_t)B_ * L_ * H_];         // attention out fp32
__device__ float g_pr[(size_t)B_ * L_ * H_];         // o-proj out fp32

#define MODE_PLAIN 0
#define MODE_QK    1   // transposed per head: [b,head,d,l]
#define MODE_V     2   // row-major per head:  [b,head,l,d]

__device__ __forceinline__ unsigned f2tf(float x) {
    unsigned u;
    asm("cvt.rna.tf32.f32 %0, %1;" : "=r"(u) : "f"(x));
    return u;
}

__device__ __forceinline__ void mma_tf32(float c[4], const unsigned a[4], const unsigned b[2]) {
    asm volatile(
        "mma.sync.aligned.m16n8k8.row.col.f32.tf32.tf32.f32 "
        "{%0,%1,%2,%3},{%4,%5,%6,%7},{%8,%9},{%0,%1,%2,%3};\n"
        : "+f"(c[0]), "+f"(c[1]), "+f"(c[2]), "+f"(c[3])
        : "r"(a[0]), "r"(a[1]), "r"(a[2]), "r"(a[3]), "r"(b[0]), "r"(b[1]));
}

// swizzled index, 32-float rows (float granularity)
__device__ __forceinline__ int swz32(int r, int c) {
    return r * 32 + ((((c >> 2) ^ (r & 7)) << 2) | (c & 3));
}
// swizzled index, 128-float rows
__device__ __forceinline__ int swz128(int r, int c) {
    return r * 128 + ((((c >> 2) ^ (r & 7)) << 2) | (c & 3));
}

// ---------------- tf32 tensor-core GEMM: C = A[M,2048] @ W[N,2048]^T + bias ----------------
__global__ __launch_bounds__(256, 1)
void gemm_tc(const float* __restrict__ A,
             const float* __restrict__ W, const float* __restrict__ bias,
             float* __restrict__ C, int mode,
             int N, int heads, int tf32out,
             const float* __restrict__ W2, const float* __restrict__ bias2,
             float* __restrict__ C2, int mode2)
{
    if (blockIdx.z == 1) { W = W2; bias = bias2; C = C2; mode = mode2; }
    const int K = H_;

    extern __shared__ unsigned sm[];
    unsigned* AsB = sm;          // [2][128*32]
    unsigned* BsB = sm + 8192;   // [2][128*32]

    int tid = threadIdx.x;
    int wid = tid >> 5, lane = tid & 31;
    int g = lane >> 2, tig = lane & 3;
    int warp_m = (wid & 3) * 32;
    int warp_n = (wid >> 2) * 64;
    int m0 = blockIdx.y * 128;
    int n0 = blockIdx.x * 128;

    const float* Ab = A + (size_t)m0 * K;
    const float* Wb = W + (size_t)n0 * K;

    float acc[2][8][4];
#pragma unroll
    for (int mt = 0; mt < 2; mt++)
#pragma unroll
        for (int nt = 0; nt < 8; nt++)
#pragma unroll
            for (int i = 0; i < 4; i++) acc[mt][nt][i] = 0.f;

    float4 pa[4], pb[4];

    // prologue: load k0 = 0
#pragma unroll
    for (int i = 0; i < 4; i++) {
        int idx = tid + i * 256;
        int r = idx >> 3, c4 = idx & 7;
        pa[i] = *(const float4*)&Ab[(size_t)r * K + c4 * 4];
        pb[i] = *(const float4*)&Wb[(size_t)r * K + c4 * 4];
    }
#pragma unroll
    for (int i = 0; i < 4; i++) {
        int idx = tid + i * 256;
        int r = idx >> 3, c4 = idx & 7;
        int pc4 = c4 ^ (r & 7);
        uint4 ua = make_uint4(f2tf(pa[i].x), f2tf(pa[i].y), f2tf(pa[i].z), f2tf(pa[i].w));
        uint4 ub = make_uint4(f2tf(pb[i].x), f2tf(pb[i].y), f2tf(pb[i].z), f2tf(pb[i].w));
        *(uint4*)&AsB[r * 32 + pc4 * 4] = ua;
        *(uint4*)&BsB[r * 32 + pc4 * 4] = ub;
    }
    __syncthreads();

    for (int s = 0; s < 64; s++) {
        int cur = s & 1;
        if (s < 63) {
            int k0 = (s + 1) * 32;
#pragma unroll
            for (int i = 0; i < 4; i++) {
                int idx = tid + i * 256;
                int r = idx >> 3, c4 = idx & 7;
                pa[i] = *(const float4*)&Ab[(size_t)r * K + k0 + c4 * 4];
                pb[i] = *(const float4*)&Wb[(size_t)r * K + k0 + c4 * 4];
            }
        }
        const unsigned* Ac = AsB + cur * 4096;
        const unsigned* Bc = BsB + cur * 4096;
#pragma unroll
        for (int kc = 0; kc < 4; kc++) {
            int kb = kc * 8;
            unsigned af[2][4], bf[8][2];
#pragma unroll
            for (int mt = 0; mt < 2; mt++) {
                int r = warp_m + mt * 16 + g;
                af[mt][0] = Ac[swz32(r,     kb + tig)];
                af[mt][1] = Ac[swz32(r + 8, kb + tig)];
                af[mt][2] = Ac[swz32(r,     kb + tig + 4)];
                af[mt][3] = Ac[swz32(r + 8, kb + tig + 4)];
            }
#pragma unroll
            for (int nt = 0; nt < 8; nt++) {
                int rn = warp_n + nt * 8 + g;
                bf[nt][0] = Bc[swz32(rn, kb + tig)];
                bf[nt][1] = Bc[swz32(rn, kb + tig + 4)];
            }
#pragma unroll
            for (int mt = 0; mt < 2; mt++)
#pragma unroll
                for (int nt = 0; nt < 8; nt++)
                    mma_tf32(acc[mt][nt], af[mt], bf[nt]);
        }
        if (s < 63) {
            unsigned* An = AsB + (cur ^ 1) * 4096;
            unsigned* Bn = BsB + (cur ^ 1) * 4096;
#pragma unroll
            for (int i = 0; i < 4; i++) {
                int idx = tid + i * 256;
                int r = idx >> 3, c4 = idx & 7;
                int pc4 = c4 ^ (r & 7);
                uint4 ua = make_uint4(f2tf(pa[i].x), f2tf(pa[i].y), f2tf(pa[i].z), f2tf(pa[i].w));
                uint4 ub = make_uint4(f2tf(pb[i].x), f2tf(pb[i].y), f2tf(pb[i].z), f2tf(pb[i].w));
                *(uint4*)&An[r * 32 + pc4 * 4] = ua;
                *(uint4*)&Bn[r * 32 + pc4 * 4] = ub;
            }
        }
        __syncthreads();
    }

    // epilogue
    int b  = m0 / L_;
    int l0 = m0 % L_;
    int h  = n0 / D_;

#pragma unroll
    for (int mt = 0; mt < 2; mt++) {
#pragma unroll
        for (int nt = 0; nt < 8; nt++) {
            int coln = warp_n + nt * 8 + 2 * tig;          // col within 128-tile
            float b0 = bias[n0 + coln], b1 = bias[n0 + coln + 1];
            float v0 = acc[mt][nt][0] + b0;
            float v1 = acc[mt][nt][1] + b1;
            float v2 = acc[mt][nt][2] + b0;
            float v3 = acc[mt][nt][3] + b1;
            if (tf32out) {
                v0 = __uint_as_float(f2tf(v0));
                v1 = __uint_as_float(f2tf(v1));
                v2 = __uint_as_float(f2tf(v2));
                v3 = __uint_as_float(f2tf(v3));
            }
            int rloc = warp_m + mt * 16 + g;
            if (mode == MODE_PLAIN) {
                float* p = C + (size_t)(m0 + rloc) * N + n0 + coln;
                *(float2*)p = make_float2(v0, v1);
                *(float2*)(p + (size_t)8 * N) = make_float2(v2, v3);
            } else if (mode == MODE_V) {
                float* base = C + ((size_t)(b * heads + h)) * L_ * D_;
                float* p = base + (size_t)(l0 + rloc) * D_ + coln;
                *(float2*)p = make_float2(v0, v1);
                *(float2*)(p + (size_t)8 * D_) = make_float2(v2, v3);
            } else { // MODE_QK: [d][l]
                float* base = C + ((size_t)(b * heads + h)) * D_ * L_;
                float* p0 = base + (size_t)coln * L_ + l0 + rloc;
                float* p1 = p0 + L_;
                p0[0] = v0; p0[8] = v2;
                p1[0] = v1; p1[8] = v3;
            }
        }
    }
}

// ---------------- flash attention, tf32 tensor cores ----------------
// Q tile 64 rows, KV tiles 128. 8 warps: 2(M) x 4(N), warp tile 32x32.
// Cross-warp softmax reduction through smem (4 n-warps share each q-row).
__global__ __launch_bounds__(256, 1)
void attn_tc(const unsigned* __restrict__ q, const unsigned* __restrict__ k,
             const unsigned* __restrict__ vt, const float* __restrict__ mask,
             float* __restrict__ out)
{
    extern __shared__ unsigned sm[];
    unsigned* Qs = sm;                    // 64 x 128
    unsigned* Ks = sm + 8192;             // 128 x 128 (rows = kv pos, cols = d)
    unsigned* Vs = sm + 8192 + 16384;     // 128 x 128 (rows = d, cols = kv pos)
    unsigned* Ps = sm + 8192 + 32768;     // 64 x 128
    float* maxbuf = (float*)(sm + 49152); // [64][4]
    float* sumbuf = maxbuf + 256;         // [64][4]

    int tid = threadIdx.x;
    int wid = tid >> 5, lane = tid & 31;
    int g = lane >> 2, tig = lane & 3;
    int warp_m = (wid & 1) * 32;
    int warp_n = (wid >> 1) * 32;
    int widn = wid >> 1;                  // n-warp index 0..3
    int bh = blockIdx.y;
    int b = bh / NH_, h = bh % NH_, kvh = h / G_;
    int q0 = blockIdx.x * 64;

    const uint4* qg = (const uint4*)(q + ((size_t)(b * NH_ + h)) * L_ * D_ + (size_t)q0 * D_);
    const unsigned* kg = k  + ((size_t)(b * KVH_ + kvh)) * L_ * D_;
    const unsigned* vg = vt + ((size_t)(b * KVH_ + kvh)) * D_ * L_;
    const float* mrow = mask + (size_t)b * L_;

    // load Q (2048 uint4)
#pragma unroll
    for (int i = 0; i < 8; i++) {
        int idx = tid + i * 256;
        int r = idx >> 5, c4 = idx & 31;
        int pc4 = c4 ^ (r & 7);
        *(uint4*)&Qs[r * 128 + pc4 * 4] = qg[idx];
    }

    float o[2][4][4];
#pragma unroll
    for (int mt = 0; mt < 2; mt++)
#pragma unroll
        for (int nt = 0; nt < 4; nt++)
#pragma unroll
            for (int i = 0; i < 4; i++) o[mt][nt][i] = 0.f;
    float m_run[2][2] = {{-1e30f, -1e30f}, {-1e30f, -1e30f}};
    float l_run[2][2] = {{0.f, 0.f}, {0.f, 0.f}};

    for (int it = 0; it < L_ / 128; it++) {
        int c0 = it * 128;
        __syncthreads();
#pragma unroll
        for (int i = 0; i < 16; i++) {
            int idx = tid + i * 256;
            int r = idx >> 5, c4 = idx & 31;
            int pc4 = c4 ^ (r & 7);
            *(uint4*)&Ks[r * 128 + pc4 * 4] = *(const uint4*)&kg[(size_t)(c0 + r) * D_ + c4 * 4];
            *(uint4*)&Vs[r * 128 + pc4 * 4] = *(const uint4*)&vg[(size_t)r * L_ + c0 + c4 * 4];
        }
        __syncthreads();

        // S = Q K^T
        float sc[2][4][4];
#pragma unroll
        for (int mt = 0; mt < 2; mt++)
#pragma unroll
            for (int nt = 0; nt < 4; nt++)
#pragma unroll
                for (int i = 0; i < 4; i++) sc[mt][nt][i] = 0.f;

#pragma unroll
        for (int kc = 0; kc < 16; kc++) {
            int kb = kc * 8;
            unsigned af[2][4], bf[4][2];
#pragma unroll
            for (int mt = 0; mt < 2; mt++) {
                int r = warp_m + mt * 16 + g;
                af[mt][0] = Qs[swz128(r,     kb + tig)];
                af[mt][1] = Qs[swz128(r + 8, kb + tig)];
                af[mt][2] = Qs[swz128(r,     kb + tig + 4)];
                af[mt][3] = Qs[swz128(r + 8, kb + tig + 4)];
            }
#pragma unroll
            for (int nt = 0; nt < 4; nt++) {
                int rn = warp_n + nt * 8 + g;
                bf[nt][0] = Ks[swz128(rn, kb + tig)];
                bf[nt][1] = Ks[swz128(rn, kb + tig + 4)];
            }
#pragma unroll
            for (int mt = 0; mt < 2; mt++)
#pragma unroll
                for (int nt = 0; nt < 4; nt++)
                    mma_tf32(sc[mt][nt], af[mt], bf[nt]);
        }

        // mask values per nt (2 cols each)
        float2 mv[4];
#pragma unroll
        for (int nt = 0; nt < 4; nt++)
            mv[nt] = *(const float2*)&mrow[c0 + warp_n + nt * 8 + 2 * tig];

        // pass 1: scale+mask, warp-local row max, publish to smem
#pragma unroll
        for (int mt = 0; mt < 2; mt++) {
#pragma unroll
            for (int hf = 0; hf < 2; hf++) {
                float mx = -1e30f;
#pragma unroll
                for (int nt = 0; nt < 4; nt++) {
                    float s0 = sc[mt][nt][hf * 2]     * SCALE + mv[nt].x;
                    float s1 = sc[mt][nt][hf * 2 + 1] * SCALE + mv[nt].y;
                    sc[mt][nt][hf * 2] = s0;
                    sc[mt][nt][hf * 2 + 1] = s1;
                    mx = fmaxf(mx, fmaxf(s0, s1));
                }
                mx = fmaxf(mx, __shfl_xor_sync(0xffffffffu, mx, 1));
                mx = fmaxf(mx, __shfl_xor_sync(0xffffffffu, mx, 2));
                if (tig == 0) {
                    int row = warp_m + mt * 16 + hf * 8 + g;
                    maxbuf[row * 4 + widn] = mx;
                }
            }
        }
        __syncthreads();

        // pass 2: global max, exp, partial sums, stage P
        float al[2][2];
#pragma unroll
        for (int mt = 0; mt < 2; mt++) {
#pragma unroll
            for (int hf = 0; hf < 2; hf++) {
                int row = warp_m + mt * 16 + hf * 8 + g;
                float4 m4 = *(const float4*)&maxbuf[row * 4];
                float mx = fmaxf(fmaxf(m4.x, m4.y), fmaxf(m4.z, m4.w));
                float mn = fmaxf(m_run[mt][hf], mx);
                al[mt][hf] = __expf(m_run[mt][hf] - mn);
                m_run[mt][hf] = mn;
                float rs = 0.f;
#pragma unroll
                for (int nt = 0; nt < 4; nt++) {
                    float p0 = __expf(sc[mt][nt][hf * 2]     - mn);
                    float p1 = __expf(sc[mt][nt][hf * 2 + 1] - mn);
                    sc[mt][nt][hf * 2] = p0;
                    sc[mt][nt][hf * 2 + 1] = p1;
                    rs += p0 + p1;
                }
                rs += __shfl_xor_sync(0xffffffffu, rs, 1);
                rs += __shfl_xor_sync(0xffffffffu, rs, 2);
                if (tig == 0) sumbuf[row * 4 + widn] = rs;
#pragma unroll
                for (int nt = 0; nt < 4; nt++) {
                    o[mt][nt][hf * 2]     *= al[mt][hf];
                    o[mt][nt][hf * 2 + 1] *= al[mt][hf];
                }
            }
        }

        // stage P (tf32) into smem
#pragma unroll
        for (int mt = 0; mt < 2; mt++) {
#pragma unroll
            for (int nt = 0; nt < 4; nt++) {
                int cb = warp_n + nt * 8 + 2 * tig;
                int r0 = warp_m + mt * 16 + g;
                uint2 u0 = make_uint2(f2tf(sc[mt][nt][0]), f2tf(sc[mt][nt][1]));
                uint2 u1 = make_uint2(f2tf(sc[mt][nt][2]), f2tf(sc[mt][nt][3]));
                *(uint2*)&Ps[swz128(r0, cb)] = u0;
                *(uint2*)&Ps[swz128(r0 + 8, cb)] = u1;
            }
        }
        __syncthreads();

        // combine partial sums -> l_run (consistent across warps)
#pragma unroll
        for (int mt = 0; mt < 2; mt++) {
#pragma unroll
            for (int hf = 0; hf < 2; hf++) {
                int row = warp_m + mt * 16 + hf * 8 + g;
                float4 s4 = *(const float4*)&sumbuf[row * 4];
                float rs = (s4.x + s4.y) + (s4.z + s4.w);
                l_run[mt][hf] = l_run[mt][hf] * al[mt][hf] + rs;
            }
        }

        // O += P V
#pragma unroll
        for (int kc = 0; kc < 16; kc++) {
            int kb = kc * 8;
            unsigned af[2][4], bf[4][2];
#pragma unroll
            for (int mt = 0; mt < 2; mt++) {
                int r = warp_m + mt * 16 + g;
                af[mt][0] = Ps[swz128(r,     kb + tig)];
                af[mt][1] = Ps[swz128(r + 8, kb + tig)];
                af[mt][2] = Ps[swz128(r,     kb + tig + 4)];
                af[mt][3] = Ps[swz128(r + 8, kb + tig + 4)];
            }
#pragma unroll
            for (int nt = 0; nt < 4; nt++) {
                int rn = warp_n + nt * 8 + g;       // d-row in Vs
                bf[nt][0] = Vs[swz128(rn, kb + tig)];
                bf[nt][1] = Vs[swz128(rn, kb + tig + 4)];
            }
#pragma unroll
            for (int mt = 0; mt < 2; mt++)
#pragma unroll
                for (int nt = 0; nt < 4; nt++)
                    mma_tf32(o[mt][nt], af[mt], bf[nt]);
        }
    }

    // epilogue
#pragma unroll
    for (int mt = 0; mt < 2; mt++) {
#pragma unroll
        for (int hf = 0; hf < 2; hf++) {
            float inv = 1.f / l_run[mt][hf];
            int row = q0 + warp_m + mt * 16 + g + hf * 8;
            float* op = out + ((size_t)(b * L_ + row)) * H_ + h * D_;
#pragma unroll
            for (int nt = 0; nt < 4; nt++) {
                int d = warp_n + nt * 8 + 2 * tig;
                *(float2*)&op[d] = make_float2(o[mt][nt][hf * 2] * inv,
                                               o[mt][nt][hf * 2 + 1] * inv);
            }
        }
    }
}

// ---------------- residual + LayerNorm ----------------
__global__ __launch_bounds__(256)
void ln_kernel(const float* __restrict__ proj, const float* __restrict__ x,
               const float* __restrict__ g, const float* __restrict__ bb,
               float* __restrict__ out)
{
    __shared__ float red[8];
    __shared__ float s_mu, s_rstd;
    int row = blockIdx.x;
    int tid = threadIdx.x;
    const float* pr = proj + (size_t)row * H_;
    const float* xr = x + (size_t)row * H_;

    float vals[8];
    float sum = 0.f;
#pragma unroll
    for (int t = 0; t < 8; t++) {
        int ci = tid + t * 256;
        float v = pr[ci] + xr[ci];
        vals[t] = v;
        sum += v;
    }
    for (int s = 16; s; s >>= 1) sum += __shfl_xor_sync(0xffffffffu, sum, s);
    if ((tid & 31) == 0) red[tid >> 5] = sum;
    __syncthreads();
    if (tid < 32) {
        float v = (tid < 8) ? red[tid] : 0.f;
        for (int s = 4; s; s >>= 1) v += __shfl_xor_sync(0xffffffffu, v, s);
        if (tid == 0) s_mu = v * (1.f / H_);
    }
    __syncthreads();
    float mu = s_mu;
    float vs = 0.f;
#pragma unroll
    for (int t = 0; t < 8; t++) {
        float dv = vals[t] - mu;
        vs += dv * dv;
    }
    for (int s = 16; s; s >>= 1) vs += __shfl_xor_sync(0xffffffffu, vs, s);
    if ((tid & 31) == 0) red[tid >> 5] = vs;
    __syncthreads();
    if (tid < 32) {
        float v = (tid < 8) ? red[tid] : 0.f;
        for (int s = 4; s; s >>= 1) v += __shfl_xor_sync(0xffffffffu, v, s);
        if (tid == 0) s_rstd = rsqrtf(v * (1.f / H_) + 1e-12f);
    }
    __syncthreads();
    float rstd = s_rstd;
#pragma unroll
    for (int t = 0; t < 8; t++) {
        int ci = tid + t * 256;
        out[(size_t)row * H_ + ci] = (vals[t] - mu) * rstd * g[ci] + bb[ci];
    }
}

// ---------------- launch ----------------
extern "C" void kernel_launch(void* const* d_in, const int* in_sizes, int n_in,
                              void* d_out, int out_size)
{
    const float* x    = (const float*)d_in[0];
    const float* mask = (const float*)d_in[1];
    const float* Wq   = (const float*)d_in[2];
    const float* bq   = (const float*)d_in[3];
    const float* Wk   = (const float*)d_in[4];
    const float* bk   = (const float*)d_in[5];
    const float* Wv   = (const float*)d_in[6];
    const float* bv   = (const float*)d_in[7];
    const float* Wo   = (const float*)d_in[8];
    const float* bo   = (const float*)d_in[9];
    const float* lng  = (const float*)d_in[10];
    const float* lnb  = (const float*)d_in[11];
    float* out = (float*)d_out;

    float *qb, *kb, *vtb, *at, *pr;
    cudaGetSymbolAddress((void**)&qb, g_q);
    cudaGetSymbolAddress((void**)&kb, g_k);
    cudaGetSymbolAddress((void**)&vtb, g_vt);
    cudaGetSymbolAddress((void**)&at, g_at);
    cudaGetSymbolAddress((void**)&pr, g_pr);

    cudaFuncSetAttribute((const void*)gemm_tc,
                         cudaFuncAttributeMaxDynamicSharedMemorySize, 65536);
    cudaFuncSetAttribute((const void*)attn_tc,
                         cudaFuncAttributeMaxDynamicSharedMemorySize, 200704);

    // Q projection -> [b,h,l,d] tf32
    gemm_tc<<<dim3(16, 32, 1), 256, 65536>>>(x, Wq, bq, qb, MODE_V, H_, NH_, 1,
                                             Wq, bq, qb, MODE_V);
    // K -> [b,kvh,l,d], V -> [b,kvh,d,l] (transposed), both tf32
    gemm_tc<<<dim3(4, 32, 2), 256, 65536>>>(x, Wk, bk, kb, MODE_V, KVH_ * D_, KVH_, 1,
                                            Wv, bv, vtb, MODE_QK);
    // attention
    attn_tc<<<dim3(L_ / 64, B_ * NH_), 256, 200704>>>(
        (const unsigned*)qb, (const unsigned*)kb, (const unsigned*)vtb, mask, at);
    // O projection
    gemm_tc<<<dim3(16, 32, 1), 256, 65536>>>(at, Wo, bo, pr, MODE_PLAIN, H_, 0, 0,
                                             Wo, bo, pr, MODE_PLAIN);
    // residual + layernorm
    ln_kernel<<<B_ * L_, 256>>>(pr, x, lng, lnb, out);
}

// round 5
// speedup vs baseline: 8.6200x; 2.7281x over previous
#include <cuda_runtime.h>
#include <cuda_fp16.h>
#include <math.h>

#define B_   2
#define L_   2048
#define H_   2048
#define NH_  16
#define KVH_ 4
#define G_   4
#define D_   128
#define SCALE 0.08838834764831845f   // 1/sqrt(128)

// ---------------- scratch ----------------
__device__ __half g_xh[(size_t)B_ * L_ * H_];          // X in fp16
__device__ __half g_wq[(size_t)H_ * H_];
__device__ __half g_wk[(size_t)KVH_ * D_ * H_];
__device__ __half g_wv[(size_t)KVH_ * D_ * H_];
__device__ __half g_wo[(size_t)H_ * H_];
__device__ __half g_q [(size_t)B_ * NH_  * L_ * D_];   // [b,h,l,d]
__device__ __half g_k [(size_t)B_ * KVH_ * L_ * D_];   // [b,kvh,l,d]
__device__ __half g_vt[(size_t)B_ * KVH_ * D_ * L_];   // [b,kvh,d,l]
__device__ __half g_at[(size_t)B_ * L_ * H_];          // attention out fp16
__device__ float  g_pr[(size_t)B_ * L_ * H_];          // o-proj out fp32

#define MODE_PLAIN 0
#define MODE_QK    1   // transposed per head: [b,head,d,l]  (fp16)
#define MODE_V     2   // row-major per head:  [b,head,l,d]  (fp16)

#define CP16(dst, src) asm volatile("cp.async.cg.shared.global [%0], [%1], 16;\n" :: "r"(dst), "l"(src))
#define CPCOMMIT() asm volatile("cp.async.commit_group;\n" ::)

__device__ __forceinline__ void mma_h(float c[4], const unsigned a[4], const unsigned b[2]) {
    asm volatile(
        "mma.sync.aligned.m16n8k16.row.col.f32.f16.f16.f32 "
        "{%0,%1,%2,%3},{%4,%5,%6,%7},{%8,%9},{%0,%1,%2,%3};\n"
        : "+f"(c[0]), "+f"(c[1]), "+f"(c[2]), "+f"(c[3])
        : "r"(a[0]), "r"(a[1]), "r"(a[2]), "r"(a[3]), "r"(b[0]), "r"(b[1]));
}

__device__ __forceinline__ unsigned packh2(float lo, float hi) {
    __half2 h = __floats2half2_rn(lo, hi);
    return *(unsigned*)&h;
}

// ---------------- fp32 -> fp16 conversion ----------------
__global__ __launch_bounds__(256)
void cvt4(const float4* __restrict__ s, __half* __restrict__ d, int n4) {
    int i = blockIdx.x * blockDim.x + threadIdx.x;
    if (i < n4) {
        float4 v = s[i];
        __half2* p = (__half2*)(d + (size_t)i * 4);
        p[0] = __floats2half2_rn(v.x, v.y);
        p[1] = __floats2half2_rn(v.z, v.w);
    }
}

// ---------------- fp16 tensor-core GEMM: C = A[M,2048] @ W[N,2048]^T + bias ----------------
// BM=128 BN=128 BK=64, 8 warps (4m x 2n), warp tile 32x64.
__global__ __launch_bounds__(256, 2)
void gemm_h(const __half* __restrict__ A,
            const __half* __restrict__ W, const float* __restrict__ bias,
            void* __restrict__ C, int mode, int N, int heads,
            const __half* __restrict__ W2, const float* __restrict__ bias2,
            void* __restrict__ C2, int mode2)
{
    if (blockIdx.z == 1) { W = W2; bias = bias2; C = C2; mode = mode2; }
    const int K = H_;

    extern __shared__ __half sh[];
    __half* As = sh;            // [2][128*64]
    __half* Bs = sh + 16384;    // [2][128*64]

    int tid = threadIdx.x;
    int wid = tid >> 5, lane = tid & 31;
    int g = lane >> 2, tig = lane & 3;
    int warp_m = (wid & 3) * 32;
    int warp_n = (wid >> 2) * 64;
    int m0 = blockIdx.y * 128;
    int n0 = blockIdx.x * 128;

    const __half* Ab = A + (size_t)m0 * K;
    const __half* Wb = W + (size_t)n0 * K;

    // cp.async offsets: 4 chunks of 16B per thread per operand per buffer
    int srcOff[4];
    unsigned dA0[4], dB0[4];
#pragma unroll
    for (int i = 0; i < 4; i++) {
        int idx = tid + i * 256;
        int r = idx >> 3, c8 = idx & 7;
        srcOff[i] = r * K + c8 * 8;
        int sw = c8 ^ (r & 7);
        dA0[i] = (unsigned)__cvta_generic_to_shared(As + r * 64 + sw * 8);
        dB0[i] = (unsigned)__cvta_generic_to_shared(Bs + r * 64 + sw * 8);
    }

    float acc[2][8][4];
#pragma unroll
    for (int mt = 0; mt < 2; mt++)
#pragma unroll
        for (int nt = 0; nt < 8; nt++)
#pragma unroll
            for (int i = 0; i < 4; i++) acc[mt][nt][i] = 0.f;

    // prologue: load step 0 into buf 0
#pragma unroll
    for (int i = 0; i < 4; i++) {
        CP16(dA0[i], Ab + srcOff[i]);
        CP16(dB0[i], Wb + srcOff[i]);
    }
    CPCOMMIT();

    for (int s = 0; s < 32; s++) {
        if (s + 1 < 32) {
            int k0 = (s + 1) * 64;
            unsigned boff = (unsigned)(((s + 1) & 1) * 16384);  // bytes (8192 halves)
#pragma unroll
            for (int i = 0; i < 4; i++) {
                CP16(dA0[i] + boff, Ab + srcOff[i] + k0);
                CP16(dB0[i] + boff, Wb + srcOff[i] + k0);
            }
            CPCOMMIT();
            asm volatile("cp.async.wait_group 1;\n" ::);
        } else {
            asm volatile("cp.async.wait_group 0;\n" ::);
        }
        __syncthreads();

        const __half* Ac = As + (s & 1) * 8192 + (warp_m + g) * 64;
        const __half* Bc = Bs + (s & 1) * 8192 + (warp_n + g) * 64;
#pragma unroll
        for (int ks = 0; ks < 4; ks++) {
            int x0 = (((2 * ks) ^ g) << 3) + 2 * tig;
            int x1 = (((2 * ks + 1) ^ g) << 3) + 2 * tig;
            unsigned a[2][4], b[8][2];
#pragma unroll
            for (int mt = 0; mt < 2; mt++) {
                const __half* ap = Ac + mt * 16 * 64;
                a[mt][0] = *(const unsigned*)(ap + x0);
                a[mt][1] = *(const unsigned*)(ap + 512 + x0);
                a[mt][2] = *(const unsigned*)(ap + x1);
                a[mt][3] = *(const unsigned*)(ap + 512 + x1);
            }
#pragma unroll
            for (int nt = 0; nt < 8; nt++) {
                const __half* bp = Bc + nt * 8 * 64;
                b[nt][0] = *(const unsigned*)(bp + x0);
                b[nt][1] = *(const unsigned*)(bp + x1);
            }
#pragma unroll
            for (int mt = 0; mt < 2; mt++)
#pragma unroll
                for (int nt = 0; nt < 8; nt++)
                    mma_h(acc[mt][nt], a[mt], b[nt]);
        }
        __syncthreads();
    }

    // epilogue
    int b  = m0 / L_;
    int l0 = m0 % L_;
    int h  = n0 / D_;

#pragma unroll
    for (int mt = 0; mt < 2; mt++) {
#pragma unroll
        for (int nt = 0; nt < 8; nt++) {
            int coln = warp_n + nt * 8 + 2 * tig;
            float b0 = bias[n0 + coln], b1 = bias[n0 + coln + 1];
            float v0 = acc[mt][nt][0] + b0;
            float v1 = acc[mt][nt][1] + b1;
            float v2 = acc[mt][nt][2] + b0;
            float v3 = acc[mt][nt][3] + b1;
            int rloc = warp_m + mt * 16 + g;
            if (mode == MODE_PLAIN) {
                float* p = (float*)C + (size_t)(m0 + rloc) * N + n0 + coln;
                *(float2*)p = make_float2(v0, v1);
                *(float2*)(p + (size_t)8 * N) = make_float2(v2, v3);
            } else if (mode == MODE_V) {
                __half* base = (__half*)C + ((size_t)(b * heads + h)) * L_ * D_;
                __half* p = base + (size_t)(l0 + rloc) * D_ + coln;
                *(unsigned*)p = packh2(v0, v1);
                *(unsigned*)(p + (size_t)8 * D_) = packh2(v2, v3);
            } else { // MODE_QK: [d][l]
                __half* base = (__half*)C + ((size_t)(b * heads + h)) * D_ * L_;
                __half* p0 = base + (size_t)coln * L_ + l0 + rloc;
                __half* p1 = p0 + L_;
                p0[0] = __float2half(v0); p0[8] = __float2half(v2);
                p1[0] = __float2half(v1); p1[8] = __float2half(v3);
            }
        }
    }
}

// swizzled chunk for 128-half rows: c16 in [0,16)
__device__ __forceinline__ int sw16(int r, int c16) {
    return (c16 & 8) | ((c16 ^ r) & 7);
}

// ---------------- flash attention, fp16 tensor cores ----------------
// Q tile 64, KV tile 128, 8 warps 2(M) x 4(N), warp tile 32x32.
__global__ __launch_bounds__(256, 2)
void attn_h(const __half* __restrict__ q, const __half* __restrict__ k,
            const __half* __restrict__ vt, const float* __restrict__ mask,
            __half* __restrict__ out)
{
    extern __shared__ __half sh[];
    __half* Qs = sh;              // 64 x 128
    __half* Ks = sh + 8192;       // 128 x 128 (rows = kv, cols = d)
    __half* Vs = sh + 24576;      // 128 x 128 (rows = d, cols = kv)
    __half* Ps = sh + 40960;      // 64 x 128
    float* maxbuf = (float*)(sh + 49152);  // [64][4]
    float* sumbuf = maxbuf + 256;

    int tid = threadIdx.x;
    int wid = tid >> 5, lane = tid & 31;
    int g = lane >> 2, tig = lane & 3;
    int warp_m = (wid & 1) * 32;
    int warp_n = (wid >> 1) * 32;
    int widn = wid >> 1;
    int bh = blockIdx.y;
    int b = bh / NH_, h = bh % NH_, kvh = h / G_;
    int q0 = blockIdx.x * 64;

    const __half* qg = q  + ((size_t)(b * NH_ + h)) * L_ * D_ + (size_t)q0 * D_;
    const __half* kg = k  + ((size_t)(b * KVH_ + kvh)) * L_ * D_;
    const __half* vg = vt + ((size_t)(b * KVH_ + kvh)) * D_ * L_;
    const float* mrow = mask + (size_t)b * L_;

    // issue Q loads (committed with first K/V group)
#pragma unroll
    for (int i = 0; i < 4; i++) {
        int idx = tid + i * 256;
        int r = idx >> 4, c16 = idx & 15;
        unsigned dst = (unsigned)__cvta_generic_to_shared(Qs + r * 128 + sw16(r, c16) * 8);
        CP16(dst, qg + r * D_ + c16 * 8);
    }

    // K/V per-thread cp.async offsets
    unsigned dK[8], dV[8];
    int rK[8], cK[8];
#pragma unroll
    for (int i = 0; i < 8; i++) {
        int idx = tid + i * 256;
        int r = idx >> 4, c16 = idx & 15;
        rK[i] = r; cK[i] = c16;
        dK[i] = (unsigned)__cvta_generic_to_shared(Ks + r * 128 + sw16(r, c16) * 8);
        dV[i] = (unsigned)__cvta_generic_to_shared(Vs + r * 128 + sw16(r, c16) * 8);
    }

    float o[2][4][4];
#pragma unroll
    for (int mt = 0; mt < 2; mt++)
#pragma unroll
        for (int nt = 0; nt < 4; nt++)
#pragma unroll
            for (int i = 0; i < 4; i++) o[mt][nt][i] = 0.f;
    float m_run[2][2] = {{-1e30f, -1e30f}, {-1e30f, -1e30f}};
    float l_run[2][2] = {{0.f, 0.f}, {0.f, 0.f}};

    for (int it = 0; it < L_ / 128; it++) {
        int c0 = it * 128;
        __syncthreads();   // all consumers of Ks/Vs/Ps done
#pragma unroll
        for (int i = 0; i < 8; i++) {
            CP16(dK[i], kg + (size_t)(c0 + rK[i]) * D_ + cK[i] * 8);
            CP16(dV[i], vg + (size_t)rK[i] * L_ + c0 + cK[i] * 8);
        }
        CPCOMMIT();
        asm volatile("cp.async.wait_group 0;\n" ::);
        __syncthreads();

        // S = Q K^T
        float sc[2][4][4];
#pragma unroll
        for (int mt = 0; mt < 2; mt++)
#pragma unroll
            for (int nt = 0; nt < 4; nt++)
#pragma unroll
                for (int i = 0; i < 4; i++) sc[mt][nt][i] = 0.f;

        const __half* Qc = Qs + (warp_m + g) * 128;
        const __half* Kc = Ks + (warp_n + g) * 128;
#pragma unroll
        for (int ks = 0; ks < 8; ks++) {
            int x0 = (sw16(g, 2 * ks) << 3) + 2 * tig;
            int x1 = (sw16(g, 2 * ks + 1) << 3) + 2 * tig;
            unsigned a[2][4], bfr[4][2];
#pragma unroll
            for (int mt = 0; mt < 2; mt++) {
                const __half* ap = Qc + mt * 16 * 128;
                a[mt][0] = *(const unsigned*)(ap + x0);
                a[mt][1] = *(const unsigned*)(ap + 1024 + x0);
                a[mt][2] = *(const unsigned*)(ap + x1);
                a[mt][3] = *(const unsigned*)(ap + 1024 + x1);
            }
#pragma unroll
            for (int nt = 0; nt < 4; nt++) {
                const __half* bp = Kc + nt * 8 * 128;
                bfr[nt][0] = *(const unsigned*)(bp + x0);
                bfr[nt][1] = *(const unsigned*)(bp + x1);
            }
#pragma unroll
            for (int mt = 0; mt < 2; mt++)
#pragma unroll
                for (int nt = 0; nt < 4; nt++)
                    mma_h(sc[mt][nt], a[mt], bfr[nt]);
        }

        float2 mv[4];
#pragma unroll
        for (int nt = 0; nt < 4; nt++)
            mv[nt] = *(const float2*)&mrow[c0 + warp_n + nt * 8 + 2 * tig];

        // pass 1: scale+mask, warp-local max -> smem
#pragma unroll
        for (int mt = 0; mt < 2; mt++) {
#pragma unroll
            for (int hf = 0; hf < 2; hf++) {
                float mx = -1e30f;
#pragma unroll
                for (int nt = 0; nt < 4; nt++) {
                    float s0 = sc[mt][nt][hf * 2]     * SCALE + mv[nt].x;
                    float s1 = sc[mt][nt][hf * 2 + 1] * SCALE + mv[nt].y;
                    sc[mt][nt][hf * 2] = s0;
                    sc[mt][nt][hf * 2 + 1] = s1;
                    mx = fmaxf(mx, fmaxf(s0, s1));
                }
                mx = fmaxf(mx, __shfl_xor_sync(0xffffffffu, mx, 1));
                mx = fmaxf(mx, __shfl_xor_sync(0xffffffffu, mx, 2));
                if (tig == 0) {
                    int row = warp_m + mt * 16 + hf * 8 + g;
                    maxbuf[row * 4 + widn] = mx;
                }
            }
        }
        __syncthreads();

        // pass 2: global max, exp, partial sums, stage P (fp16)
        float al[2][2];
#pragma unroll
        for (int mt = 0; mt < 2; mt++) {
#pragma unroll
            for (int hf = 0; hf < 2; hf++) {
                int row = warp_m + mt * 16 + hf * 8 + g;
                float4 m4 = *(const float4*)&maxbuf[row * 4];
                float mx = fmaxf(fmaxf(m4.x, m4.y), fmaxf(m4.z, m4.w));
                float mn = fmaxf(m_run[mt][hf], mx);
                al[mt][hf] = __expf(m_run[mt][hf] - mn);
                m_run[mt][hf] = mn;
                float rs = 0.f;
#pragma unroll
                for (int nt = 0; nt < 4; nt++) {
                    float p0 = __expf(sc[mt][nt][hf * 2]     - mn);
                    float p1 = __expf(sc[mt][nt][hf * 2 + 1] - mn);
                    sc[mt][nt][hf * 2] = p0;
                    sc[mt][nt][hf * 2 + 1] = p1;
                    rs += p0 + p1;
                }
                rs += __shfl_xor_sync(0xffffffffu, rs, 1);
                rs += __shfl_xor_sync(0xffffffffu, rs, 2);
                if (tig == 0) sumbuf[row * 4 + widn] = rs;
#pragma unroll
                for (int nt = 0; nt < 4; nt++) {
                    o[mt][nt][hf * 2]     *= al[mt][hf];
                    o[mt][nt][hf * 2 + 1] *= al[mt][hf];
                }
            }
        }

        // stage P as fp16
#pragma unroll
        for (int mt = 0; mt < 2; mt++) {
#pragma unroll
            for (int nt = 0; nt < 4; nt++) {
                int cb = warp_n + nt * 8 + 2 * tig;
                int ch = cb >> 3, w = cb & 7;
                int r0 = warp_m + mt * 16 + g;
                *(unsigned*)&Ps[r0 * 128 + sw16(r0, ch) * 8 + w] =
                    packh2(sc[mt][nt][0], sc[mt][nt][1]);
                *(unsigned*)&Ps[(r0 + 8) * 128 + sw16(r0, ch) * 8 + w] =
                    packh2(sc[mt][nt][2], sc[mt][nt][3]);
            }
        }
        __syncthreads();

        // combine partial sums
#pragma unroll
        for (int mt = 0; mt < 2; mt++) {
#pragma unroll
            for (int hf = 0; hf < 2; hf++) {
                int row = warp_m + mt * 16 + hf * 8 + g;
                float4 s4 = *(const float4*)&sumbuf[row * 4];
                l_run[mt][hf] = l_run[mt][hf] * al[mt][hf] + (s4.x + s4.y) + (s4.z + s4.w);
            }
        }

        // O += P V
        const __half* Pc = Ps + (warp_m + g) * 128;
        const __half* Vc = Vs + (warp_n + g) * 128;
#pragma unroll
        for (int ks = 0; ks < 8; ks++) {
            int x0 = (sw16(g, 2 * ks) << 3) + 2 * tig;
            int x1 = (sw16(g, 2 * ks + 1) << 3) + 2 * tig;
            unsigned a[2][4], bfr[4][2];
#pragma unroll
            for (int mt = 0; mt < 2; mt++) {
                const __half* ap = Pc + mt * 16 * 128;
                a[mt][0] = *(const unsigned*)(ap + x0);
                a[mt][1] = *(const unsigned*)(ap + 1024 + x0);
                a[mt][2] = *(const unsigned*)(ap + x1);
                a[mt][3] = *(const unsigned*)(ap + 1024 + x1);
            }
#pragma unroll
            for (int nt = 0; nt < 4; nt++) {
                const __half* bp = Vc + nt * 8 * 128;
                bfr[nt][0] = *(const unsigned*)(bp + x0);
                bfr[nt][1] = *(const unsigned*)(bp + x1);
            }
#pragma unroll
            for (int mt = 0; mt < 2; mt++)
#pragma unroll
                for (int nt = 0; nt < 4; nt++)
                    mma_h(o[mt][nt], a[mt], bfr[nt]);
        }
    }

    // epilogue (fp16 out)
#pragma unroll
    for (int mt = 0; mt < 2; mt++) {
#pragma unroll
        for (int hf = 0; hf < 2; hf++) {
            float inv = 1.f / l_run[mt][hf];
            int row = q0 + warp_m + mt * 16 + g + hf * 8;
            __half* op = out + ((size_t)(b * L_ + row)) * H_ + h * D_;
#pragma unroll
            for (int nt = 0; nt < 4; nt++) {
                int d = warp_n + nt * 8 + 2 * tig;
                *(unsigned*)&op[d] = packh2(o[mt][nt][hf * 2] * inv,
                                            o[mt][nt][hf * 2 + 1] * inv);
            }
        }
    }
}

// ---------------- residual + LayerNorm ----------------
__global__ __launch_bounds__(256)
void ln_kernel(const float* __restrict__ proj, const float* __restrict__ x,
               const float* __restrict__ g, const float* __restrict__ bb,
               float* __restrict__ out)
{
    __shared__ float red[8];
    __shared__ float s_mu, s_rstd;
    int row = blockIdx.x;
    int tid = threadIdx.x;
    const float* pr = proj + (size_t)row * H_;
    const float* xr = x + (size_t)row * H_;

    float vals[8];
    float sum = 0.f;
#pragma unroll
    for (int t = 0; t < 8; t++) {
        int ci = tid + t * 256;
        float v = pr[ci] + xr[ci];
        vals[t] = v;
        sum += v;
    }
    for (int s = 16; s; s >>= 1) sum += __shfl_xor_sync(0xffffffffu, sum, s);
    if ((tid & 31) == 0) red[tid >> 5] = sum;
    __syncthreads();
    if (tid < 32) {
        float v = (tid < 8) ? red[tid] : 0.f;
        for (int s = 4; s; s >>= 1) v += __shfl_xor_sync(0xffffffffu, v, s);
        if (tid == 0) s_mu = v * (1.f / H_);
    }
    __syncthreads();
    float mu = s_mu;
    float vs = 0.f;
#pragma unroll
    for (int t = 0; t < 8; t++) {
        float dv = vals[t] - mu;
        vs += dv * dv;
    }
    for (int s = 16; s; s >>= 1) vs += __shfl_xor_sync(0xffffffffu, vs, s);
    if ((tid & 31) == 0) red[tid >> 5] = vs;
    __syncthreads();
    if (tid < 32) {
        float v = (tid < 8) ? red[tid] : 0.f;
        for (int s = 4; s; s >>= 1) v += __shfl_xor_sync(0xffffffffu, v, s);
        if (tid == 0) s_rstd = rsqrtf(v * (1.f / H_) + 1e-12f);
    }
    __syncthreads();
    float rstd = s_rstd;
#pragma unroll
    for (int t = 0; t < 8; t++) {
        int ci = tid + t * 256;
        out[(size_t)row * H_ + ci] = (vals[t] - mu) * rstd * g[ci] + bb[ci];
    }
}

// ---------------- launch ----------------
extern "C" void kernel_launch(void* const* d_in, const int* in_sizes, int n_in,
                              void* d_out, int out_size)
{
    const float* x    = (const float*)d_in[0];
    const float* mask = (const float*)d_in[1];
    const float* Wq   = (const float*)d_in[2];
    const float* bq   = (const float*)d_in[3];
    const float* Wk   = (const float*)d_in[4];
    const float* bk   = (const float*)d_in[5];
    const float* Wv   = (const float*)d_in[6];
    const float* bv   = (const float*)d_in[7];
    const float* Wo   = (const float*)d_in[8];
    const float* bo   = (const float*)d_in[9];
    const float* lng  = (const float*)d_in[10];
    const float* lnb  = (const float*)d_in[11];
    float* out = (float*)d_out;

    __half *xh, *wqh, *wkh, *wvh, *woh, *qb, *kb, *vtb, *at;
    float *pr;
    cudaGetSymbolAddress((void**)&xh,  g_xh);
    cudaGetSymbolAddress((void**)&wqh, g_wq);
    cudaGetSymbolAddress((void**)&wkh, g_wk);
    cudaGetSymbolAddress((void**)&wvh, g_wv);
    cudaGetSymbolAddress((void**)&woh, g_wo);
    cudaGetSymbolAddress((void**)&qb,  g_q);
    cudaGetSymbolAddress((void**)&kb,  g_k);
    cudaGetSymbolAddress((void**)&vtb, g_vt);
    cudaGetSymbolAddress((void**)&at,  g_at);
    cudaGetSymbolAddress((void**)&pr,  g_pr);

    cudaFuncSetAttribute((const void*)gemm_h,
                         cudaFuncAttributeMaxDynamicSharedMemorySize, 65536);
    cudaFuncSetAttribute((const void*)attn_h,
                         cudaFuncAttributeMaxDynamicSharedMemorySize, 100352);

    // fp32 -> fp16 pre-pass
    cvt4<<<8192, 256>>>((const float4*)x,  xh,  2097152);
    cvt4<<<4096, 256>>>((const float4*)Wq, wqh, 1048576);
    cvt4<<<1024, 256>>>((const float4*)Wk, wkh, 262144);
    cvt4<<<1024, 256>>>((const float4*)Wv, wvh, 262144);
    cvt4<<<4096, 256>>>((const float4*)Wo, woh, 1048576);

    // Q projection -> [b,h,l,d] fp16
    gemm_h<<<dim3(16, 32, 1), 256, 65536>>>(xh, wqh, bq, qb, MODE_V, H_, NH_,
                                            wqh, bq, qb, MODE_V);
    // K -> [b,kvh,l,d], V -> [b,kvh,d,l]
    gemm_h<<<dim3(4, 32, 2), 256, 65536>>>(xh, wkh, bk, kb, MODE_V, KVH_ * D_, KVH_,
                                           wvh, bv, vtb, MODE_QK);
    // attention
    attn_h<<<dim3(L_ / 64, B_ * NH_), 256, 100352>>>(qb, kb, vtb, mask, at);
    // O projection (fp32 out)
    gemm_h<<<dim3(16, 32, 1), 256, 65536>>>(at, woh, bo, pr, MODE_PLAIN, H_, 0,
                                            woh, bo, pr, MODE_PLAIN);
    // residual + layernorm
    ln_kernel<<<B_ * L_, 256>>>(pr, x, lng, lnb, out);
}

// round 7
// speedup vs baseline: 9.6284x; 1.1170x over previous
#include <cuda_runtime.h>
#include <cuda_fp16.h>
#include <math.h>
#include <stdint.h>

#define B_   2
#define L_   2048
#define H_   2048
#define NH_  16
#define KVH_ 4
#define G_   4
#define D_   128
#define SCALE 0.08838834764831845f   // 1/sqrt(128)

// ---------------- scratch ----------------
__device__ __half g_xh[(size_t)B_ * L_ * H_];
__device__ __half g_wq[(size_t)H_ * H_];
__device__ __half g_wk[(size_t)KVH_ * D_ * H_];
__device__ __half g_wv[(size_t)KVH_ * D_ * H_];
__device__ __half g_wo[(size_t)H_ * H_];
__device__ __half g_q [(size_t)B_ * NH_  * L_ * D_];   // [b,h,l,d]
__device__ __half g_k [(size_t)B_ * KVH_ * L_ * D_];   // [b,kvh,l,d]
__device__ __half g_vt[(size_t)B_ * KVH_ * D_ * L_];   // [b,kvh,d,l]
__device__ __half g_at[(size_t)B_ * L_ * H_];          // attention out fp16
__device__ float  g_pr[(size_t)B_ * L_ * H_];          // o-proj out fp32

#define MODE_PLAIN 0
#define MODE_QK    1   // transposed per head: [b,head,d,l]  (fp16)
#define MODE_V     2   // row-major per head:  [b,head,l,d]  (fp16)

#define CP16(dst, src) asm volatile("cp.async.cg.shared.global [%0], [%1], 16;\n" :: "r"(dst), "l"(src))
#define CPCOMMIT() asm volatile("cp.async.commit_group;\n" ::)

__device__ __forceinline__ void mma_h(float c[4], const unsigned a[4], const unsigned b[2]) {
    asm volatile(
        "mma.sync.aligned.m16n8k16.row.col.f32.f16.f16.f32 "
        "{%0,%1,%2,%3},{%4,%5,%6,%7},{%8,%9},{%0,%1,%2,%3};\n"
        : "+f"(c[0]), "+f"(c[1]), "+f"(c[2]), "+f"(c[3])
        : "r"(a[0]), "r"(a[1]), "r"(a[2]), "r"(a[3]), "r"(b[0]), "r"(b[1]));
}

__device__ __forceinline__ void ldsm4(unsigned &r0, unsigned &r1, unsigned &r2, unsigned &r3, uint32_t a) {
    asm volatile("ldmatrix.sync.aligned.m8n8.x4.shared.b16 {%0,%1,%2,%3}, [%4];"
        : "=r"(r0), "=r"(r1), "=r"(r2), "=r"(r3) : "r"(a));
}

__device__ __forceinline__ unsigned packh2(float lo, float hi) {
    __half2 h = __floats2half2_rn(lo, hi);
    return *(unsigned*)&h;
}

// ---------------- fused fp32 -> fp16 conversion ----------------
#define CVT_N0 2097152   // x
#define CVT_N1 3145728   // +Wq
#define CVT_N2 3407872   // +Wk
#define CVT_N3 3670016   // +Wv

__global__ __launch_bounds__(256)
void cvt_all(const float4* __restrict__ x, const float4* __restrict__ wq,
             const float4* __restrict__ wk, const float4* __restrict__ wv,
             const float4* __restrict__ wo,
             __half* __restrict__ xh, __half* __restrict__ wqh,
             __half* __restrict__ wkh, __half* __restrict__ wvh,
             __half* __restrict__ woh)
{
    int i = blockIdx.x * 256 + threadIdx.x;
    const float4* s; __half* d; int off;
    if (i < CVT_N0)      { s = x;  d = xh;  off = i; }
    else if (i < CVT_N1) { s = wq; d = wqh; off = i - CVT_N0; }
    else if (i < CVT_N2) { s = wk; d = wkh; off = i - CVT_N1; }
    else if (i < CVT_N3) { s = wv; d = wvh; off = i - CVT_N2; }
    else                 { s = wo; d = woh; off = i - CVT_N3; }
    float4 v = s[off];
    __half2* p = (__half2*)(d + (size_t)off * 4);
    p[0] = __floats2half2_rn(v.x, v.y);
    p[1] = __floats2half2_rn(v.z, v.w);
}

// ---------------- fp16 mma GEMM: C = A[M,2048] @ W[N,2048]^T + bias ----------------
// BM=128 BN=128 BK=64, 3-stage cp.async, 8 warps (4m x 2n), warp tile 32x64.
// ldmatrix fragment loads. smem: A 3x16KB at [0,49152), B 3x16KB at [49152,98304).
__global__ __launch_bounds__(256, 2)
void gemm_h(const __half* __restrict__ A,
            const __half* __restrict__ W, const float* __restrict__ bias,
            void* __restrict__ C, int mode, int N, int heads,
            const __half* __restrict__ W2, const float* __restrict__ bias2,
            void* __restrict__ C2, int mode2)
{
    if (blockIdx.z == 1) { W = W2; bias = bias2; C = C2; mode = mode2; }
    const int K = H_;

    extern __shared__ __align__(1024) __half sh[];
    uint32_t sb = (uint32_t)__cvta_generic_to_shared(sh);

    int tid = threadIdx.x;
    int wid = tid >> 5, lane = tid & 31;
    int warp_m = (wid & 3) * 32;
    int warp_n = (wid >> 2) * 64;
    int m0 = blockIdx.y * 128;
    int n0 = blockIdx.x * 128;

    const __half* Ab = A + (size_t)m0 * K;
    const __half* Wb = W + (size_t)n0 * K;

    // cp.async slots: 4 chunks per operand per thread (128 rows x 8 chunks)
    uint32_t dA0[4], dB0[4];
    int srcOff[4];
#pragma unroll
    for (int i = 0; i < 4; i++) {
        int idx = tid + i * 256;
        int r = idx >> 3, c8 = idx & 7;
        srcOff[i] = r * K + c8 * 8;
        int sw = c8 ^ (r & 7);
        dA0[i] = sb + (r * 64 + sw * 8) * 2;
        dB0[i] = sb + 49152 + (r * 64 + sw * 8) * 2;
    }

    // ldmatrix lane geometry
    int laneq = lane & 7;
    int h8a = (lane >> 3) & 1, ksa = lane >> 4;        // A: matrix row-half / k-half
    int h8b = lane >> 4,       ksb = (lane >> 3) & 1;  // B: matrix row-half / k-half
    uint32_t aRow[2], bRow[4];
#pragma unroll
    for (int mt = 0; mt < 2; mt++)
        aRow[mt] = sb + ((warp_m + mt * 16 + laneq + h8a * 8) * 64) * 2;
#pragma unroll
    for (int np = 0; np < 4; np++)
        bRow[np] = sb + 49152 + ((warp_n + np * 16 + laneq + h8b * 8) * 64) * 2;

    float acc[2][8][4];
#pragma unroll
    for (int mt = 0; mt < 2; mt++)
#pragma unroll
        for (int nt = 0; nt < 8; nt++)
#pragma unroll
            for (int i = 0; i < 4; i++) acc[mt][nt][i] = 0.f;

    // prologue: chunks 0,1 -> stages 0,1
#pragma unroll
    for (int i = 0; i < 4; i++) { CP16(dA0[i], Ab + srcOff[i]); CP16(dB0[i], Wb + srcOff[i]); }
    CPCOMMIT();
#pragma unroll
    for (int i = 0; i < 4; i++) { CP16(dA0[i] + 16384, Ab + srcOff[i] + 64); CP16(dB0[i] + 16384, Wb + srcOff[i] + 64); }
    CPCOMMIT();

    int st = 0;
    for (int s = 0; s < 32; s++) {
        asm volatile("cp.async.wait_group 1;\n" ::);
        __syncthreads();
        if (s + 2 < 32) {
            int st2 = st + 2; if (st2 >= 3) st2 -= 3;
            unsigned boff = (unsigned)(st2 * 16384);
            int k0 = (s + 2) * 64;
#pragma unroll
            for (int i = 0; i < 4; i++) {
                CP16(dA0[i] + boff, Ab + srcOff[i] + k0);
                CP16(dB0[i] + boff, Wb + srcOff[i] + k0);
            }
            CPCOMMIT();
        }
        unsigned soff = (unsigned)(st * 16384);
#pragma unroll
        for (int ks = 0; ks < 4; ks++) {
            unsigned xa = (unsigned)((((2 * ks + ksa) ^ laneq) << 4));
            unsigned xb = (unsigned)((((2 * ks + ksb) ^ laneq) << 4));
            unsigned a[2][4], b[8][2];
#pragma unroll
            for (int mt = 0; mt < 2; mt++)
                ldsm4(a[mt][0], a[mt][1], a[mt][2], a[mt][3], aRow[mt] + soff + xa);
#pragma unroll
            for (int np = 0; np < 4; np++)
                ldsm4(b[2 * np][0], b[2 * np][1], b[2 * np + 1][0], b[2 * np + 1][1],
                      bRow[np] + soff + xb);
#pragma unroll
            for (int mt = 0; mt < 2; mt++)
#pragma unroll
                for (int nt = 0; nt < 8; nt++)
                    mma_h(acc[mt][nt], a[mt], b[nt]);
        }
        __syncthreads();
        st = st + 1; if (st >= 3) st = 0;
    }

    // epilogue
    int g = lane >> 2, tig = lane & 3;
    int b  = m0 / L_;
    int l0 = m0 % L_;
    int h  = n0 / D_;

#pragma unroll
    for (int mt = 0; mt < 2; mt++) {
#pragma unroll
        for (int nt = 0; nt < 8; nt++) {
            int coln = warp_n + nt * 8 + 2 * tig;
            float b0 = bias[n0 + coln], b1 = bias[n0 + coln + 1];
            float v0 = acc[mt][nt][0] + b0;
            float v1 = acc[mt][nt][1] + b1;
            float v2 = acc[mt][nt][2] + b0;
            float v3 = acc[mt][nt][3] + b1;
            int rloc = warp_m + mt * 16 + g;
            if (mode == MODE_PLAIN) {
                float* p = (float*)C + (size_t)(m0 + rloc) * N + n0 + coln;
                *(float2*)p = make_float2(v0, v1);
                *(float2*)(p + (size_t)8 * N) = make_float2(v2, v3);
            } else if (mode == MODE_V) {
                __half* base = (__half*)C + ((size_t)(b * heads + h)) * L_ * D_;
                __half* p = base + (size_t)(l0 + rloc) * D_ + coln;
                *(unsigned*)p = packh2(v0, v1);
                *(unsigned*)(p + (size_t)8 * D_) = packh2(v2, v3);
            } else { // MODE_QK: [d][l]
                __half* base = (__half*)C + ((size_t)(b * heads + h)) * D_ * L_;
                __half* p0 = base + (size_t)coln * L_ + l0 + rloc;
                __half* p1 = p0 + L_;
                p0[0] = __float2half(v0); p0[8] = __float2half(v2);
                p1[0] = __float2half(v1); p1[8] = __float2half(v3);
            }
        }
    }
}

// swizzled chunk for 128-half rows: c16 in [0,16)
__device__ __forceinline__ int sw16(int r, int c16) {
    return (c16 & 8) | ((c16 ^ r) & 7);
}

// ---------------- flash attention, fp16 mma + ldmatrix ----------------
// Q tile 64, KV tile 128, 8 warps 2(M) x 4(N), warp tile 32x32.
__global__ __launch_bounds__(256, 2)
void attn_h(const __half* __restrict__ q, const __half* __restrict__ k,
            const __half* __restrict__ vt, const float* __restrict__ mask,
            __half* __restrict__ out)
{
    extern __shared__ __half sh[];
    __half* Qs = sh;              // 64 x 128
    __half* Ks = sh + 8192;       // 128 x 128 (rows = kv, cols = d)
    __half* Vs = sh + 24576;      // 128 x 128 (rows = d, cols = kv)
    __half* Ps = sh + 40960;      // 64 x 128
    float* maxbuf = (float*)(sh + 49152);  // [64][4]
    float* sumbuf = maxbuf + 256;
    uint32_t sb = (uint32_t)__cvta_generic_to_shared(sh);

    int tid = threadIdx.x;
    int wid = tid >> 5, lane = tid & 31;
    int g = lane >> 2, tig = lane & 3;
    int warp_m = (wid & 1) * 32;
    int warp_n = (wid >> 1) * 32;
    int widn = wid >> 1;
    int bh = blockIdx.y;
    int b = bh / NH_, h = bh % NH_, kvh = h / G_;
    int q0 = blockIdx.x * 64;

    const __half* qg = q  + ((size_t)(b * NH_ + h)) * L_ * D_ + (size_t)q0 * D_;
    const __half* kg = k  + ((size_t)(b * KVH_ + kvh)) * L_ * D_;
    const __half* vg = vt + ((size_t)(b * KVH_ + kvh)) * D_ * L_;
    const float* mrow = mask + (size_t)b * L_;

#pragma unroll
    for (int i = 0; i < 4; i++) {
        int idx = tid + i * 256;
        int r = idx >> 4, c16 = idx & 15;
        unsigned dst = sb + (r * 128 + sw16(r, c16) * 8) * 2;
        CP16(dst, qg + r * D_ + c16 * 8);
    }

    unsigned dK[8], dV[8];
    int rK[8], cK[8];
#pragma unroll
    for (int i = 0; i < 8; i++) {
        int idx = tid + i * 256;
        int r = idx >> 4, c16 = idx & 15;
        rK[i] = r; cK[i] = c16;
        dK[i] = sb + 16384 + (r * 128 + sw16(r, c16) * 8) * 2;
        dV[i] = sb + 49152 + (r * 128 + sw16(r, c16) * 8) * 2;
    }

    // ldmatrix lane geometry (row stride 128 halves = 256B)
    int laneq = lane & 7;
    int h8a = (lane >> 3) & 1, ksa = lane >> 4;
    int h8b = lane >> 4,       ksb = (lane >> 3) & 1;
    uint32_t qRow[2], pRow[2], kRow[2], vRow[2];
#pragma unroll
    for (int mt = 0; mt < 2; mt++) {
        int r = warp_m + mt * 16 + laneq + h8a * 8;
        qRow[mt] = sb + (r * 128) * 2;
        pRow[mt] = sb + 81920 + (r * 128) * 2;   // Ps at 40960 halves
    }
#pragma unroll
    for (int np = 0; np < 2; np++) {
        int r = warp_n + np * 16 + laneq + h8b * 8;
        kRow[np] = sb + 16384 + (r * 128) * 2;
        vRow[np] = sb + 49152 + (r * 128) * 2;
    }

    float o[2][4][4];
#pragma unroll
    for (int mt = 0; mt < 2; mt++)
#pragma unroll
        for (int nt = 0; nt < 4; nt++)
#pragma unroll
            for (int i = 0; i < 4; i++) o[mt][nt][i] = 0.f;
    float m_run[2][2] = {{-1e30f, -1e30f}, {-1e30f, -1e30f}};
    float l_run[2][2] = {{0.f, 0.f}, {0.f, 0.f}};

    for (int it = 0; it < L_ / 128; it++) {
        int c0 = it * 128;
        __syncthreads();
#pragma unroll
        for (int i = 0; i < 8; i++) {
            CP16(dK[i], kg + (size_t)(c0 + rK[i]) * D_ + cK[i] * 8);
            CP16(dV[i], vg + (size_t)rK[i] * L_ + c0 + cK[i] * 8);
        }
        CPCOMMIT();
        asm volatile("cp.async.wait_group 0;\n" ::);
        __syncthreads();

        // S = Q K^T
        float sc[2][4][4];
#pragma unroll
        for (int mt = 0; mt < 2; mt++)
#pragma unroll
            for (int nt = 0; nt < 4; nt++)
#pragma unroll
                for (int i = 0; i < 4; i++) sc[mt][nt][i] = 0.f;

#pragma unroll
        for (int ks = 0; ks < 8; ks++) {
            int kca = 2 * ks + ksa, kcb = 2 * ks + ksb;
            unsigned xa = (unsigned)(((kca & 8) | ((kca ^ laneq) & 7)) << 4);
            unsigned xb = (unsigned)(((kcb & 8) | ((kcb ^ laneq) & 7)) << 4);
            unsigned a[2][4], bfr[4][2];
#pragma unroll
            for (int mt = 0; mt < 2; mt++)
                ldsm4(a[mt][0], a[mt][1], a[mt][2], a[mt][3], qRow[mt] + xa);
#pragma unroll
            for (int np = 0; np < 2; np++)
                ldsm4(bfr[2 * np][0], bfr[2 * np][1], bfr[2 * np + 1][0], bfr[2 * np + 1][1],
                      kRow[np] + xb);
#pragma unroll
            for (int mt = 0; mt < 2; mt++)
#pragma unroll
                for (int nt = 0; nt < 4; nt++)
                    mma_h(sc[mt][nt], a[mt], bfr[nt]);
        }

        float2 mv[4];
#pragma unroll
        for (int nt = 0; nt < 4; nt++)
            mv[nt] = *(const float2*)&mrow[c0 + warp_n + nt * 8 + 2 * tig];

        // pass 1: scale+mask, warp-local max -> smem
#pragma unroll
        for (int mt = 0; mt < 2; mt++) {
#pragma unroll
            for (int hf = 0; hf < 2; hf++) {
                float mx = -1e30f;
#pragma unroll
                for (int nt = 0; nt < 4; nt++) {
                    float s0 = sc[mt][nt][hf * 2]     * SCALE + mv[nt].x;
                    float s1 = sc[mt][nt][hf * 2 + 1] * SCALE + mv[nt].y;
                    sc[mt][nt][hf * 2] = s0;
                    sc[mt][nt][hf * 2 + 1] = s1;
                    mx = fmaxf(mx, fmaxf(s0, s1));
                }
                mx = fmaxf(mx, __shfl_xor_sync(0xffffffffu, mx, 1));
                mx = fmaxf(mx, __shfl_xor_sync(0xffffffffu, mx, 2));
                if (tig == 0) {
                    int row = warp_m + mt * 16 + hf * 8 + g;
                    maxbuf[row * 4 + widn] = mx;
                }
            }
        }
        __syncthreads();

        // pass 2: global max, exp, partial sums, stage P
        float al[2][2];
#pragma unroll
        for (int mt = 0; mt < 2; mt++) {
#pragma unroll
            for (int hf = 0; hf < 2; hf++) {
                int row = warp_m + mt * 16 + hf * 8 + g;
                float4 m4 = *(const float4*)&maxbuf[row * 4];
                float mx = fmaxf(fmaxf(m4.x, m4.y), fmaxf(m4.z, m4.w));
                float mn = fmaxf(m_run[mt][hf], mx);
                al[mt][hf] = __expf(m_run[mt][hf] - mn);
                m_run[mt][hf] = mn;
                float rs = 0.f;
#pragma unroll
                for (int nt = 0; nt < 4; nt++) {
                    float p0 = __expf(sc[mt][nt][hf * 2]     - mn);
                    float p1 = __expf(sc[mt][nt][hf * 2 + 1] - mn);
                    sc[mt][nt][hf * 2] = p0;
                    sc[mt][nt][hf * 2 + 1] = p1;
                    rs += p0 + p1;
                }
                rs += __shfl_xor_sync(0xffffffffu, rs, 1);
                rs += __shfl_xor_sync(0xffffffffu, rs, 2);
                if (tig == 0) sumbuf[row * 4 + widn] = rs;
#pragma unroll
                for (int nt = 0; nt < 4; nt++) {
                    o[mt][nt][hf * 2]     *= al[mt][hf];
                    o[mt][nt][hf * 2 + 1] *= al[mt][hf];
                }
            }
        }

        // stage P as fp16
#pragma unroll
        for (int mt = 0; mt < 2; mt++) {
#pragma unroll
            for (int nt = 0; nt < 4; nt++) {
                int cb = warp_n + nt * 8 + 2 * tig;
                int ch = cb >> 3, w = cb & 7;
                int r0 = warp_m + mt * 16 + g;
                *(unsigned*)&Ps[r0 * 128 + sw16(r0, ch) * 8 + w] =
                    packh2(sc[mt][nt][0], sc[mt][nt][1]);
                *(unsigned*)&Ps[(r0 + 8) * 128 + sw16(r0, ch) * 8 + w] =
                    packh2(sc[mt][nt][2], sc[mt][nt][3]);
            }
        }
        __syncthreads();

#pragma unroll
        for (int mt = 0; mt < 2; mt++) {
#pragma unroll
            for (int hf = 0; hf < 2; hf++) {
                int row = warp_m + mt * 16 + hf * 8 + g;
                float4 s4 = *(const float4*)&sumbuf[row * 4];
                l_run[mt][hf] = l_run[mt][hf] * al[mt][hf] + (s4.x + s4.y) + (s4.z + s4.w);
            }
        }

        // O += P V
#pragma unroll
        for (int ks = 0; ks < 8; ks++) {
            int kca = 2 * ks + ksa, kcb = 2 * ks + ksb;
            unsigned xa = (unsigned)(((kca & 8) | ((kca ^ laneq) & 7)) << 4);
            unsigned xb = (unsigned)(((kcb & 8) | ((kcb ^ laneq) & 7)) << 4);
            unsigned a[2][4], bfr[4][2];
#pragma unroll
            for (int mt = 0; mt < 2; mt++)
                ldsm4(a[mt][0], a[mt][1], a[mt][2], a[mt][3], pRow[mt] + xa);
#pragma unroll
            for (int np = 0; np < 2; np++)
                ldsm4(bfr[2 * np][0], bfr[2 * np][1], bfr[2 * np + 1][0], bfr[2 * np + 1][1],
                      vRow[np] + xb);
#pragma unroll
            for (int mt = 0; mt < 2; mt++)
#pragma unroll
                for (int nt = 0; nt < 4; nt++)
                    mma_h(o[mt][nt], a[mt], bfr[nt]);
        }
    }

    // epilogue (fp16 out)
#pragma unroll
    for (int mt = 0; mt < 2; mt++) {
#pragma unroll
        for (int hf = 0; hf < 2; hf++) {
            float inv = 1.f / l_run[mt][hf];
            int row = q0 + warp_m + mt * 16 + g + hf * 8;
            __half* op = out + ((size_t)(b * L_ + row)) * H_ + h * D_;
#pragma unroll
            for (int nt = 0; nt < 4; nt++) {
                int d = warp_n + nt * 8 + 2 * tig;
                *(unsigned*)&op[d] = packh2(o[mt][nt][hf * 2] * inv,
                                            o[mt][nt][hf * 2 + 1] * inv);
            }
        }
    }
}

// ---------------- residual + LayerNorm ----------------
__global__ __launch_bounds__(256)
void ln_kernel(const float* __restrict__ proj, const float* __restrict__ x,
               const float* __restrict__ g, const float* __restrict__ bb,
               float* __restrict__ out)
{
    __shared__ float red[8];
    __shared__ float s_mu, s_rstd;
    int row = blockIdx.x;
    int tid = threadIdx.x;
    const float* pr = proj + (size_t)row * H_;
    const float* xr = x + (size_t)row * H_;

    float vals[8];
    float sum = 0.f;
#pragma unroll
    for (int t = 0; t < 8; t++) {
        int ci = tid + t * 256;
        float v = pr[ci] + xr[ci];
        vals[t] = v;
        sum += v;
    }
    for (int s = 16; s; s >>= 1) sum += __shfl_xor_sync(0xffffffffu, sum, s);
    if ((tid & 31) == 0) red[tid >> 5] = sum;
    __syncthreads();
    if (tid < 32) {
        float v = (tid < 8) ? red[tid] : 0.f;
        for (int s = 4; s; s >>= 1) v += __shfl_xor_sync(0xffffffffu, v, s);
        if (tid == 0) s_mu = v * (1.f / H_);
    }
    __syncthreads();
    float mu = s_mu;
    float vs = 0.f;
#pragma unroll
    for (int t = 0; t < 8; t++) {
        float dv = vals[t] - mu;
        vs += dv * dv;
    }
    for (int s = 16; s; s >>= 1) vs += __shfl_xor_sync(0xffffffffu, vs, s);
    if ((tid & 31) == 0) red[tid >> 5] = vs;
    __syncthreads();
    if (tid < 32) {
        float v = (tid < 8) ? red[tid] : 0.f;
        for (int s = 4; s; s >>= 1) v += __shfl_xor_sync(0xffffffffu, v, s);
        if (tid == 0) s_rstd = rsqrtf(v * (1.f / H_) + 1e-12f);
    }
    __syncthreads();
    float rstd = s_rstd;
#pragma unroll
    for (int t = 0; t < 8; t++) {
        int ci = tid + t * 256;
        out[(size_t)row * H_ + ci] = (vals[t] - mu) * rstd * g[ci] + bb[ci];
    }
}

// ---------------- launch ----------------
extern "C" void kernel_launch(void* const* d_in, const int* in_sizes, int n_in,
                              void* d_out, int out_size)
{
    const float* x    = (const float*)d_in[0];
    const float* mask = (const float*)d_in[1];
    const float* Wq   = (const float*)d_in[2];
    const float* bq   = (const float*)d_in[3];
    const float* Wk   = (const float*)d_in[4];
    const float* bk   = (const float*)d_in[5];
    const float* Wv   = (const float*)d_in[6];
    const float* bv   = (const float*)d_in[7];
    const float* Wo   = (const float*)d_in[8];
    const float* bo   = (const float*)d_in[9];
    const float* lng  = (const float*)d_in[10];
    const float* lnb  = (const float*)d_in[11];
    float* out = (float*)d_out;

    __half *xh, *wqh, *wkh, *wvh, *woh, *qb, *kb, *vtb, *at;
    float *pr;
    cudaGetSymbolAddress((void**)&xh,  g_xh);
    cudaGetSymbolAddress((void**)&wqh, g_wq);
    cudaGetSymbolAddress((void**)&wkh, g_wk);
    cudaGetSymbolAddress((void**)&wvh, g_wv);
    cudaGetSymbolAddress((void**)&woh, g_wo);
    cudaGetSymbolAddress((void**)&qb,  g_q);
    cudaGetSymbolAddress((void**)&kb,  g_k);
    cudaGetSymbolAddress((void**)&vtb, g_vt);
    cudaGetSymbolAddress((void**)&at,  g_at);
    cudaGetSymbolAddress((void**)&pr,  g_pr);

    cudaFuncSetAttribute((const void*)gemm_h,
                         cudaFuncAttributeMaxDynamicSharedMemorySize, 98304);
    cudaFuncSetAttribute((const void*)attn_h,
                         cudaFuncAttributeMaxDynamicSharedMemorySize, 100352);

    // fused fp32 -> fp16 pre-pass
    cvt_all<<<18432, 256>>>((const float4*)x, (const float4*)Wq, (const float4*)Wk,
                            (const float4*)Wv, (const float4*)Wo,
                            xh, wqh, wkh, wvh, woh);

    // Q projection -> [b,h,l,d] fp16
    gemm_h<<<dim3(16, 32, 1), 256, 98304>>>(xh, wqh, bq, qb, MODE_V, H_, NH_,
                                            wqh, bq, qb, MODE_V);
    // K -> [b,kvh,l,d], V -> [b,kvh,d,l]
    gemm_h<<<dim3(4, 32, 2), 256, 98304>>>(xh, wkh, bk, kb, MODE_V, KVH_ * D_, KVH_,
                                           wvh, bv, vtb, MODE_QK);
    // attention
    attn_h<<<dim3(L_ / 64, B_ * NH_), 256, 100352>>>(qb, kb, vtb, mask, at);
    // O projection (fp32 out)
    gemm_h<<<dim3(16, 32, 1), 256, 98304>>>(at, woh, bo, pr, MODE_PLAIN, H_, 0,
                                            woh, bo, pr, MODE_PLAIN);
    // residual + layernorm
    ln_kernel<<<B_ * L_, 256>>>(pr, x, lng, lnb, out);
}

// round 8
// speedup vs baseline: 9.6744x; 1.0048x over previous
#include <cuda_runtime.h>
#include <cuda_fp16.h>
#include <math.h>
#include <stdint.h>

#define B_   2
#define L_   2048
#define H_   2048
#define NH_  16
#define KVH_ 4
#define G_   4
#define D_   128
#define SCALE 0.08838834764831845f    // 1/sqrt(128)
#define LOG2E 1.4426950408889634f
#define QSCALE (0.08838834764831845f * 1.4426950408889634f)

// ---------------- scratch ----------------
__device__ __half g_xh[(size_t)B_ * L_ * H_];
__device__ __half g_wq[(size_t)H_ * H_];
__device__ __half g_wk[(size_t)KVH_ * D_ * H_];
__device__ __half g_wv[(size_t)KVH_ * D_ * H_];
__device__ __half g_wo[(size_t)H_ * H_];
__device__ __half g_q [(size_t)B_ * NH_  * L_ * D_];   // [b,h,l,d]  (pre-scaled by QSCALE)
__device__ __half g_k [(size_t)B_ * KVH_ * L_ * D_];   // [b,kvh,l,d]
__device__ __half g_vt[(size_t)B_ * KVH_ * D_ * L_];   // [b,kvh,d,l]
__device__ __half g_at[(size_t)B_ * L_ * H_];          // attention out fp16
__device__ float  g_pr[(size_t)B_ * L_ * H_];          // o-proj out fp32

#define MODE_PLAIN 0
#define MODE_QK    1   // transposed per head: [b,head,d,l]  (fp16)
#define MODE_V     2   // row-major per head:  [b,head,l,d]  (fp16)

#define CP16(dst, src) asm volatile("cp.async.cg.shared.global [%0], [%1], 16;\n" :: "r"(dst), "l"(src))
#define CPCOMMIT() asm volatile("cp.async.commit_group;\n" ::)

__device__ __forceinline__ void mma_h(float c[4], const unsigned a[4], const unsigned b[2]) {
    asm volatile(
        "mma.sync.aligned.m16n8k16.row.col.f32.f16.f16.f32 "
        "{%0,%1,%2,%3},{%4,%5,%6,%7},{%8,%9},{%0,%1,%2,%3};\n"
        : "+f"(c[0]), "+f"(c[1]), "+f"(c[2]), "+f"(c[3])
        : "r"(a[0]), "r"(a[1]), "r"(a[2]), "r"(a[3]), "r"(b[0]), "r"(b[1]));
}

__device__ __forceinline__ void ldsm4(unsigned &r0, unsigned &r1, unsigned &r2, unsigned &r3, uint32_t a) {
    asm volatile("ldmatrix.sync.aligned.m8n8.x4.shared.b16 {%0,%1,%2,%3}, [%4];"
        : "=r"(r0), "=r"(r1), "=r"(r2), "=r"(r3) : "r"(a));
}

__device__ __forceinline__ unsigned packh2(float lo, float hi) {
    __half2 h = __floats2half2_rn(lo, hi);
    return *(unsigned*)&h;
}

// ---------------- fused fp32 -> fp16 conversion ----------------
#define CVT_N0 2097152
#define CVT_N1 3145728
#define CVT_N2 3407872
#define CVT_N3 3670016

__global__ __launch_bounds__(256)
void cvt_all(const float4* __restrict__ x, const float4* __restrict__ wq,
             const float4* __restrict__ wk, const float4* __restrict__ wv,
             const float4* __restrict__ wo,
             __half* __restrict__ xh, __half* __restrict__ wqh,
             __half* __restrict__ wkh, __half* __restrict__ wvh,
             __half* __restrict__ woh)
{
    int i = blockIdx.x * 256 + threadIdx.x;
    const float4* s; __half* d; int off;
    if (i < CVT_N0)      { s = x;  d = xh;  off = i; }
    else if (i < CVT_N1) { s = wq; d = wqh; off = i - CVT_N0; }
    else if (i < CVT_N2) { s = wk; d = wkh; off = i - CVT_N1; }
    else if (i < CVT_N3) { s = wv; d = wvh; off = i - CVT_N2; }
    else                 { s = wo; d = woh; off = i - CVT_N3; }
    float4 v = s[off];
    __half2* p = (__half2*)(d + (size_t)off * 4);
    p[0] = __floats2half2_rn(v.x, v.y);
    p[1] = __floats2half2_rn(v.z, v.w);
}

// ---------------- fp16 mma GEMM (unchanged structure from R7, + output scale) ----------------
__global__ __launch_bounds__(256, 2)
void gemm_h(const __half* __restrict__ A,
            const __half* __restrict__ W, const float* __restrict__ bias,
            void* __restrict__ C, int mode, int N, int heads, float osc,
            const __half* __restrict__ W2, const float* __restrict__ bias2,
            void* __restrict__ C2, int mode2, float osc2)
{
    if (blockIdx.z == 1) { W = W2; bias = bias2; C = C2; mode = mode2; osc = osc2; }
    const int K = H_;

    extern __shared__ __align__(1024) __half sh[];
    uint32_t sb = (uint32_t)__cvta_generic_to_shared(sh);

    int tid = threadIdx.x;
    int wid = tid >> 5, lane = tid & 31;
    int warp_m = (wid & 3) * 32;
    int warp_n = (wid >> 2) * 64;
    int m0 = blockIdx.y * 128;
    int n0 = blockIdx.x * 128;

    const __half* Ab = A + (size_t)m0 * K;
    const __half* Wb = W + (size_t)n0 * K;

    uint32_t dA0[4], dB0[4];
    int srcOff[4];
#pragma unroll
    for (int i = 0; i < 4; i++) {
        int idx = tid + i * 256;
        int r = idx >> 3, c8 = idx & 7;
        srcOff[i] = r * K + c8 * 8;
        int sw = c8 ^ (r & 7);
        dA0[i] = sb + (r * 64 + sw * 8) * 2;
        dB0[i] = sb + 49152 + (r * 64 + sw * 8) * 2;
    }

    int laneq = lane & 7;
    int ksa = lane >> 4;
    int ksb = (lane >> 3) & 1;
    uint32_t aRow[2], bRow[4];
#pragma unroll
    for (int mt = 0; mt < 2; mt++)
        aRow[mt] = sb + ((warp_m + mt * 16 + laneq + ((lane >> 3) & 1) * 8) * 64) * 2;
#pragma unroll
    for (int np = 0; np < 4; np++)
        bRow[np] = sb + 49152 + ((warp_n + np * 16 + laneq + (lane >> 4) * 8) * 64) * 2;

    float acc[2][8][4];
#pragma unroll
    for (int mt = 0; mt < 2; mt++)
#pragma unroll
        for (int nt = 0; nt < 8; nt++)
#pragma unroll
            for (int i = 0; i < 4; i++) acc[mt][nt][i] = 0.f;

#pragma unroll
    for (int i = 0; i < 4; i++) { CP16(dA0[i], Ab + srcOff[i]); CP16(dB0[i], Wb + srcOff[i]); }
    CPCOMMIT();
#pragma unroll
    for (int i = 0; i < 4; i++) { CP16(dA0[i] + 16384, Ab + srcOff[i] + 64); CP16(dB0[i] + 16384, Wb + srcOff[i] + 64); }
    CPCOMMIT();

    int st = 0;
    for (int s = 0; s < 32; s++) {
        asm volatile("cp.async.wait_group 1;\n" ::);
        __syncthreads();
        if (s + 2 < 32) {
            int st2 = st + 2; if (st2 >= 3) st2 -= 3;
            unsigned boff = (unsigned)(st2 * 16384);
            int k0 = (s + 2) * 64;
#pragma unroll
            for (int i = 0; i < 4; i++) {
                CP16(dA0[i] + boff, Ab + srcOff[i] + k0);
                CP16(dB0[i] + boff, Wb + srcOff[i] + k0);
            }
            CPCOMMIT();
        }
        unsigned soff = (unsigned)(st * 16384);
#pragma unroll
        for (int ks = 0; ks < 4; ks++) {
            unsigned xa = (unsigned)((((2 * ks + ksa) ^ laneq) << 4));
            unsigned xb = (unsigned)((((2 * ks + ksb) ^ laneq) << 4));
            unsigned a[2][4], b[8][2];
#pragma unroll
            for (int mt = 0; mt < 2; mt++)
                ldsm4(a[mt][0], a[mt][1], a[mt][2], a[mt][3], aRow[mt] + soff + xa);
#pragma unroll
            for (int np = 0; np < 4; np++)
                ldsm4(b[2 * np][0], b[2 * np][1], b[2 * np + 1][0], b[2 * np + 1][1],
                      bRow[np] + soff + xb);
#pragma unroll
            for (int mt = 0; mt < 2; mt++)
#pragma unroll
                for (int nt = 0; nt < 8; nt++)
                    mma_h(acc[mt][nt], a[mt], b[nt]);
        }
        __syncthreads();
        st = st + 1; if (st >= 3) st = 0;
    }

    int g = lane >> 2, tig = lane & 3;
    int b  = m0 / L_;
    int l0 = m0 % L_;
    int h  = n0 / D_;

#pragma unroll
    for (int mt = 0; mt < 2; mt++) {
#pragma unroll
        for (int nt = 0; nt < 8; nt++) {
            int coln = warp_n + nt * 8 + 2 * tig;
            float b0 = bias[n0 + coln], b1 = bias[n0 + coln + 1];
            float v0 = (acc[mt][nt][0] + b0) * osc;
            float v1 = (acc[mt][nt][1] + b1) * osc;
            float v2 = (acc[mt][nt][2] + b0) * osc;
            float v3 = (acc[mt][nt][3] + b1) * osc;
            int rloc = warp_m + mt * 16 + g;
            if (mode == MODE_PLAIN) {
                float* p = (float*)C + (size_t)(m0 + rloc) * N + n0 + coln;
                *(float2*)p = make_float2(v0, v1);
                *(float2*)(p + (size_t)8 * N) = make_float2(v2, v3);
            } else if (mode == MODE_V) {
                __half* base = (__half*)C + ((size_t)(b * heads + h)) * L_ * D_;
                __half* p = base + (size_t)(l0 + rloc) * D_ + coln;
                *(unsigned*)p = packh2(v0, v1);
                *(unsigned*)(p + (size_t)8 * D_) = packh2(v2, v3);
            } else { // MODE_QK: [d][l]
                __half* base = (__half*)C + ((size_t)(b * heads + h)) * D_ * L_;
                __half* p0 = base + (size_t)coln * L_ + l0 + rloc;
                __half* p1 = p0 + L_;
                p0[0] = __float2half(v0); p0[8] = __float2half(v2);
                p1[0] = __float2half(v1); p1[8] = __float2half(v3);
            }
        }
    }
}

// swizzled chunk for 128-half rows: c16 in [0,16)
__device__ __forceinline__ int sw16(int r, int c16) {
    return (c16 & 8) | ((c16 ^ r) & 7);
}

// ---------------- flash attention: warp-owns-row, register-resident P ----------------
// Q tile 128 rows, KV tile 128. 8 warps, each m=16 q-rows x full 128 kv.
// smem (bytes): Q [0,32768); K stages [32768,98304); V stages [98304,163840).
__global__ __launch_bounds__(256, 1)
void attn_h(const __half* __restrict__ q, const __half* __restrict__ k,
            const __half* __restrict__ vt, const float* __restrict__ mask,
            __half* __restrict__ out)
{
    extern __shared__ __align__(1024) __half sh[];
    uint32_t sb = (uint32_t)__cvta_generic_to_shared(sh);

    int tid = threadIdx.x;
    int wid = tid >> 5, lane = tid & 31;
    int g = lane >> 2, tig = lane & 3;
    int laneq = lane & 7;
    int ksa = lane >> 4;            // A fragment k-half select
    int h8a = (lane >> 3) & 1;      // A fragment row-half select
    int ksb = (lane >> 3) & 1;      // B fragment k-half select
    int h8b = lane >> 4;            // B fragment row-half select
    int warp_m = wid * 16;

    int bh = blockIdx.y;
    int b = bh / NH_, h = bh % NH_, kvh = h / G_;
    int q0 = blockIdx.x * 128;

    const __half* qg = q  + ((size_t)(b * NH_ + h) * L_ + q0) * D_;
    const __half* kg = k  + ((size_t)(b * KVH_ + kvh)) * L_ * D_;
    const __half* vg = vt + ((size_t)(b * KVH_ + kvh)) * D_ * L_;
    const float* mrow = mask + (size_t)b * L_;

    // Q load: 128 x 128 halves
#pragma unroll
    for (int i = 0; i < 8; i++) {
        int idx = tid + i * 256;
        int r = idx >> 4, c16 = idx & 15;
        CP16(sb + (r * 128 + sw16(r, c16) * 8) * 2, qg + r * D_ + c16 * 8);
    }
    CPCOMMIT();

    // K/V slots (stage 0 base)
    uint32_t dK[8];
    int sK[8], sV[8];
#pragma unroll
    for (int i = 0; i < 8; i++) {
        int idx = tid + i * 256;
        int r = idx >> 4, c16 = idx & 15;
        dK[i] = sb + 32768 + (r * 128 + sw16(r, c16) * 8) * 2;
        sK[i] = r * D_ + c16 * 8;
        sV[i] = r * L_ + c16 * 8;
    }
    // prologue: stage 0
#pragma unroll
    for (int i = 0; i < 8; i++) {
        CP16(dK[i], kg + sK[i]);
        CP16(dK[i] + 65536, vg + sV[i]);
    }
    CPCOMMIT();

    float o[16][4];
#pragma unroll
    for (int nt = 0; nt < 16; nt++)
#pragma unroll
        for (int i = 0; i < 4; i++) o[nt][i] = 0.f;
    float m_run[2] = {-1e30f, -1e30f};
    float l_run[2] = {0.f, 0.f};

    uint32_t qRow = sb + ((warp_m + laneq + h8a * 8) * 128) * 2;
    uint32_t bRowOff = (uint32_t)((laneq + h8b * 8) * 256);

    for (int it = 0; it < L_ / 128; it++) {
        asm volatile("cp.async.wait_group 0;\n" ::);
        __syncthreads();
        int cur = it & 1;
        uint32_t stK = sb + 32768 + cur * 32768;
        uint32_t stV = sb + 98304 + cur * 32768;
        if (it + 1 < L_ / 128) {
            int c0n = (it + 1) * 128;
            unsigned nso = (unsigned)(((it + 1) & 1) * 32768);
#pragma unroll
            for (int i = 0; i < 8; i++) {
                CP16(dK[i] + nso, kg + sK[i] + c0n * D_);
                CP16(dK[i] + nso + 65536, vg + sV[i] + c0n);
            }
            CPCOMMIT();
        }
        int c0 = it * 128;

        // S = Q K^T  (m16 x n128, k=128)
        float sc[16][4];
#pragma unroll
        for (int nt = 0; nt < 16; nt++)
#pragma unroll
            for (int i = 0; i < 4; i++) sc[nt][i] = 0.f;

#pragma unroll
        for (int ks = 0; ks < 8; ks++) {
            int kca = 2 * ks + ksa, kcb = 2 * ks + ksb;
            unsigned xa = (unsigned)(((kca & 8) | ((kca ^ laneq) & 7)) << 4);
            unsigned xb = (unsigned)(((kcb & 8) | ((kcb ^ laneq) & 7)) << 4);
            unsigned a[4];
            ldsm4(a[0], a[1], a[2], a[3], qRow + xa);
#pragma unroll
            for (int nt2 = 0; nt2 < 8; nt2++) {
                unsigned b0, b1, b2, b3;
                ldsm4(b0, b1, b2, b3, stK + nt2 * 4096 + bRowOff + xb);
                unsigned bb0[2] = {b0, b1}, bb1[2] = {b2, b3};
                mma_h(sc[2 * nt2],     a, bb0);
                mma_h(sc[2 * nt2 + 1], a, bb1);
            }
        }

        // add mask (log2 domain; Q pre-scaled by SCALE*log2e)
#pragma unroll
        for (int nt = 0; nt < 16; nt++) {
            float2 mv = *(const float2*)&mrow[c0 + nt * 8 + 2 * tig];
            sc[nt][0] = fmaf(mv.x, LOG2E, sc[nt][0]);
            sc[nt][1] = fmaf(mv.y, LOG2E, sc[nt][1]);
            sc[nt][2] = fmaf(mv.x, LOG2E, sc[nt][2]);
            sc[nt][3] = fmaf(mv.y, LOG2E, sc[nt][3]);
        }

        // warp-local online softmax (rows g and g+8; cols spread over tig lanes)
        float al[2];
#pragma unroll
        for (int hf = 0; hf < 2; hf++) {
            float mx = -1e30f;
#pragma unroll
            for (int nt = 0; nt < 16; nt++)
                mx = fmaxf(mx, fmaxf(sc[nt][hf * 2], sc[nt][hf * 2 + 1]));
            mx = fmaxf(mx, __shfl_xor_sync(0xffffffffu, mx, 1));
            mx = fmaxf(mx, __shfl_xor_sync(0xffffffffu, mx, 2));
            float mn = fmaxf(m_run[hf], mx);
            al[hf] = exp2f(m_run[hf] - mn);
            m_run[hf] = mn;
            float rs = 0.f;
#pragma unroll
            for (int nt = 0; nt < 16; nt++) {
                float p0 = exp2f(sc[nt][hf * 2]     - mn);
                float p1 = exp2f(sc[nt][hf * 2 + 1] - mn);
                sc[nt][hf * 2] = p0;
                sc[nt][hf * 2 + 1] = p1;
                rs += p0 + p1;
            }
            rs += __shfl_xor_sync(0xffffffffu, rs, 1);
            rs += __shfl_xor_sync(0xffffffffu, rs, 2);
            l_run[hf] = l_run[hf] * al[hf] + rs;
#pragma unroll
            for (int nt = 0; nt < 16; nt++) {
                o[nt][hf * 2]     *= al[hf];
                o[nt][hf * 2 + 1] *= al[hf];
            }
        }

        // O += P V   (P in registers; V from smem [d][kv])
#pragma unroll
        for (int j = 0; j < 8; j++) {
            unsigned a[4];
            a[0] = packh2(sc[2 * j][0],     sc[2 * j][1]);
            a[1] = packh2(sc[2 * j][2],     sc[2 * j][3]);
            a[2] = packh2(sc[2 * j + 1][0], sc[2 * j + 1][1]);
            a[3] = packh2(sc[2 * j + 1][2], sc[2 * j + 1][3]);
            int kcv = 2 * j + ksb;
            unsigned xv = (unsigned)(((kcv & 8) | ((kcv ^ laneq) & 7)) << 4);
#pragma unroll
            for (int nt2 = 0; nt2 < 8; nt2++) {
                unsigned b0, b1, b2, b3;
                ldsm4(b0, b1, b2, b3, stV + nt2 * 4096 + bRowOff + xv);
                unsigned bb0[2] = {b0, b1}, bb1[2] = {b2, b3};
                mma_h(o[2 * nt2],     a, bb0);
                mma_h(o[2 * nt2 + 1], a, bb1);
            }
        }
    }

    // epilogue
#pragma unroll
    for (int hf = 0; hf < 2; hf++) {
        float inv = 1.f / l_run[hf];
        int row = q0 + warp_m + hf * 8 + g;
        __half* op = out + ((size_t)(b * L_ + row)) * H_ + h * D_;
#pragma unroll
        for (int nt = 0; nt < 16; nt++)
            *(unsigned*)&op[nt * 8 + 2 * tig] = packh2(o[nt][hf * 2] * inv,
                                                       o[nt][hf * 2 + 1] * inv);
    }
}

// ---------------- residual + LayerNorm ----------------
__global__ __launch_bounds__(256)
void ln_kernel(const float* __restrict__ proj, const float* __restrict__ x,
               const float* __restrict__ g, const float* __restrict__ bb,
               float* __restrict__ out)
{
    __shared__ float red[8];
    __shared__ float s_mu, s_rstd;
    int row = blockIdx.x;
    int tid = threadIdx.x;
    const float* pr = proj + (size_t)row * H_;
    const float* xr = x + (size_t)row * H_;

    float vals[8];
    float sum = 0.f;
#pragma unroll
    for (int t = 0; t < 8; t++) {
        int ci = tid + t * 256;
        float v = pr[ci] + xr[ci];
        vals[t] = v;
        sum += v;
    }
    for (int s = 16; s; s >>= 1) sum += __shfl_xor_sync(0xffffffffu, sum, s);
    if ((tid & 31) == 0) red[tid >> 5] = sum;
    __syncthreads();
    if (tid < 32) {
        float v = (tid < 8) ? red[tid] : 0.f;
        for (int s = 4; s; s >>= 1) v += __shfl_xor_sync(0xffffffffu, v, s);
        if (tid == 0) s_mu = v * (1.f / H_);
    }
    __syncthreads();
    float mu = s_mu;
    float vs = 0.f;
#pragma unroll
    for (int t = 0; t < 8; t++) {
        float dv = vals[t] - mu;
        vs += dv * dv;
    }
    for (int s = 16; s; s >>= 1) vs += __shfl_xor_sync(0xffffffffu, vs, s);
    if ((tid & 31) == 0) red[tid >> 5] = vs;
    __syncthreads();
    if (tid < 32) {
        float v = (tid < 8) ? red[tid] : 0.f;
        for (int s = 4; s; s >>= 1) v += __shfl_xor_sync(0xffffffffu, v, s);
        if (tid == 0) s_rstd = rsqrtf(v * (1.f / H_) + 1e-12f);
    }
    __syncthreads();
    float rstd = s_rstd;
#pragma unroll
    for (int t = 0; t < 8; t++) {
        int ci = tid + t * 256;
        out[(size_t)row * H_ + ci] = (vals[t] - mu) * rstd * g[ci] + bb[ci];
    }
}

// ---------------- launch ----------------
extern "C" void kernel_launch(void* const* d_in, const int* in_sizes, int n_in,
                              void* d_out, int out_size)
{
    const float* x    = (const float*)d_in[0];
    const float* mask = (const float*)d_in[1];
    const float* Wq   = (const float*)d_in[2];
    const float* bq   = (const float*)d_in[3];
    const float* Wk   = (const float*)d_in[4];
    const float* bk   = (const float*)d_in[5];
    const float* Wv   = (const float*)d_in[6];
    const float* bv   = (const float*)d_in[7];
    const float* Wo   = (const float*)d_in[8];
    const float* bo   = (const float*)d_in[9];
    const float* lng  = (const float*)d_in[10];
    const float* lnb  = (const float*)d_in[11];
    float* out = (float*)d_out;

    __half *xh, *wqh, *wkh, *wvh, *woh, *qb, *kb, *vtb, *at;
    float *pr;
    cudaGetSymbolAddress((void**)&xh,  g_xh);
    cudaGetSymbolAddress((void**)&wqh, g_wq);
    cudaGetSymbolAddress((void**)&wkh, g_wk);
    cudaGetSymbolAddress((void**)&wvh, g_wv);
    cudaGetSymbolAddress((void**)&woh, g_wo);
    cudaGetSymbolAddress((void**)&qb,  g_q);
    cudaGetSymbolAddress((void**)&kb,  g_k);
    cudaGetSymbolAddress((void**)&vtb, g_vt);
    cudaGetSymbolAddress((void**)&at,  g_at);
    cudaGetSymbolAddress((void**)&pr,  g_pr);

    cudaFuncSetAttribute((const void*)gemm_h,
                         cudaFuncAttributeMaxDynamicSharedMemorySize, 98304);
    cudaFuncSetAttribute((const void*)attn_h,
                         cudaFuncAttributeMaxDynamicSharedMemorySize, 163840);

    // fused fp32 -> fp16 pre-pass
    cvt_all<<<18432, 256>>>((const float4*)x, (const float4*)Wq, (const float4*)Wk,
                            (const float4*)Wv, (const float4*)Wo,
                            xh, wqh, wkh, wvh, woh);

    // Q projection -> [b,h,l,d] fp16, pre-scaled by SCALE*log2e
    gemm_h<<<dim3(16, 32, 1), 256, 98304>>>(xh, wqh, bq, qb, MODE_V, H_, NH_, QSCALE,
                                            wqh, bq, qb, MODE_V, QSCALE);
    // K -> [b,kvh,l,d], V -> [b,kvh,d,l]
    gemm_h<<<dim3(4, 32, 2), 256, 98304>>>(xh, wkh, bk, kb, MODE_V, KVH_ * D_, KVH_, 1.0f,
                                           wvh, bv, vtb, MODE_QK, 1.0f);
    // attention (Q tile 128)
    attn_h<<<dim3(L_ / 128, B_ * NH_), 256, 163840>>>(qb, kb, vtb, mask, at);
    // O projection (fp32 out)
    gemm_h<<<dim3(16, 32, 1), 256, 98304>>>(at, woh, bo, pr, MODE_PLAIN, H_, 0, 1.0f,
                                            woh, bo, pr, MODE_PLAIN, 1.0f);
    // residual + layernorm
    ln_kernel<<<B_ * L_, 256>>>(pr, x, lng, lnb, out);
}